// round 10
// baseline (speedup 1.0000x reference)
#include <cuda_runtime.h>
#include <cuda_bf16.h>
#include <cstdint>
#include <math.h>

#define NND   4096
#define HID   256
#define NH    4
#define HD    64
#define DEG   32
#define NE    (NND * DEG)
#define EDIM  16
#define FFN   1024

#define WOFF_Q  0
#define WOFF_K  65536
#define WOFF_V  131072
#define WOFF_O  196608
#define WOFF_F1 262144
#define WOFF_F2 524288

// ---------------- scratch ----------------
__device__ float g_tmp[NND * HID];
__device__ float g_x1[NND * HID];
__device__ int   g_dst[NE];
__device__ int   g_ring = 1;
__device__ float g_ebias[NE * 4];

__device__ __nv_bfloat16 g_xh[NND * HID],  g_xl[NND * HID];
__device__ __nv_bfloat16 g_wh[786432],     g_wl[786432];
__device__ __nv_bfloat16 g_qh[NND * HID],  g_ql[NND * HID];
__device__ __nv_bfloat16 g_kh[NND * HID],  g_kl[NND * HID];
__device__ __nv_bfloat16 g_vh[NND * HID],  g_vl[NND * HID];
__device__ __nv_bfloat16 g_ah[NND * HID],  g_al[NND * HID];
__device__ __nv_bfloat16 g_x1h[NND * HID], g_x1l[NND * HID];
__device__ __nv_bfloat16 g_h1h[NND * FFN], g_h1l[NND * FFN];

// ---------------- merged prep: splits + edge decode + edge bias ----------------
struct SplitJob { const float* src; __nv_bfloat16* hi; __nv_bfloat16* lo; int n4; };
struct PrepP {
    SplitJob j[7];
    const int* words;
    const float *ea, *We, *be;
    float* ebias;
};

__global__ __launch_bounds__(256)
void prep_all(PrepP p) {
    int job = blockIdx.y;
    int stride = gridDim.x * blockDim.x;
    if (job < 7) {
        SplitJob jb = p.j[job];
        for (int i = blockIdx.x * blockDim.x + threadIdx.x; i < jb.n4; i += stride) {
            float4 v = ((const float4*)jb.src)[i];
            float f[4] = {v.x, v.y, v.z, v.w};
            __nv_bfloat16 h[4], l[4];
#pragma unroll
            for (int k = 0; k < 4; k++) {
                h[k] = __float2bfloat16_rn(f[k]);
                l[k] = __float2bfloat16_rn(f[k] - __bfloat162float(h[k]));
            }
            ((ushort4*)jb.hi)[i] = make_ushort4(
                __bfloat16_as_ushort(h[0]), __bfloat16_as_ushort(h[1]),
                __bfloat16_as_ushort(h[2]), __bfloat16_as_ushort(h[3]));
            ((ushort4*)jb.lo)[i] = make_ushort4(
                __bfloat16_as_ushort(l[0]), __bfloat16_as_ushort(l[1]),
                __bfloat16_as_ushort(l[2]), __bfloat16_as_ushort(l[3]));
        }
    } else if (job == 7) {
        for (int e = blockIdx.x * blockDim.x + threadIdx.x; e < NE; e += stride) {
            bool is32 = (p.words[32] == 1);
            int dst = is32 ? p.words[NE + e] : p.words[2 * NE + 2 * e];
            g_dst[e] = dst;
            int expect = ((e / DEG) + 1 + (e % DEG)) & (NND - 1);
            if (dst != expect) g_ring = 0;
        }
    } else {
        for (int e = blockIdx.x * blockDim.x + threadIdx.x; e < NE; e += stride) {
            float a0 = p.be[0], a1 = p.be[1], a2 = p.be[2], a3 = p.be[3];
            const float4* q = (const float4*)(p.ea + (size_t)e * EDIM);
#pragma unroll
            for (int c4 = 0; c4 < 4; c4++) {
                float4 x4 = q[c4];
                float xs[4] = {x4.x, x4.y, x4.z, x4.w};
#pragma unroll
                for (int i = 0; i < 4; i++) {
                    int c = c4 * 4 + i;
                    a0 += xs[i] * p.We[c * NH + 0];
                    a1 += xs[i] * p.We[c * NH + 1];
                    a2 += xs[i] * p.We[c * NH + 2];
                    a3 += xs[i] * p.We[c * NH + 3];
                }
            }
            ((float4*)p.ebias)[e] = make_float4(a0, a1, a2, a3);
        }
    }
}

// ---------------- helpers ----------------
__device__ __forceinline__ void cp16(unsigned dst, const void* src) {
    asm volatile("cp.async.cg.shared.global [%0], [%1], 16;" :: "r"(dst), "l"(src));
}
__device__ __forceinline__ void cpcommit() { asm volatile("cp.async.commit_group;"); }
__device__ __forceinline__ void ldsm4(unsigned r[4], unsigned addr) {
    asm volatile("ldmatrix.sync.aligned.m8n8.x4.shared.b16 {%0,%1,%2,%3}, [%4];"
                 : "=r"(r[0]), "=r"(r[1]), "=r"(r[2]), "=r"(r[3]) : "r"(addr));
}
__device__ __forceinline__ void ldsm4t(unsigned r[4], unsigned addr) {
    asm volatile("ldmatrix.sync.aligned.m8n8.x4.trans.shared.b16 {%0,%1,%2,%3}, [%4];"
                 : "=r"(r[0]), "=r"(r[1]), "=r"(r[2]), "=r"(r[3]) : "r"(addr));
}
__device__ __forceinline__ void mma16816(float c[4], const unsigned a[4],
                                         const unsigned b0, const unsigned b1) {
    asm volatile(
        "mma.sync.aligned.m16n8k16.row.col.f32.bf16.bf16.f32 "
        "{%0,%1,%2,%3}, {%4,%5,%6,%7}, {%8,%9}, {%0,%1,%2,%3};"
        : "+f"(c[0]), "+f"(c[1]), "+f"(c[2]), "+f"(c[3])
        : "r"(a[0]), "r"(a[1]), "r"(a[2]), "r"(a[3]), "r"(b0), "r"(b1));
}
__device__ __forceinline__ void split_pack(float v0, float v1,
                                           unsigned& hi, unsigned& lo) {
    __nv_bfloat16 h0 = __float2bfloat16_rn(v0);
    __nv_bfloat16 h1 = __float2bfloat16_rn(v1);
    __nv_bfloat16 l0 = __float2bfloat16_rn(v0 - __bfloat162float(h0));
    __nv_bfloat16 l1 = __float2bfloat16_rn(v1 - __bfloat162float(h1));
    hi = ((unsigned)__bfloat16_as_ushort(h1) << 16) | __bfloat16_as_ushort(h0);
    lo = ((unsigned)__bfloat16_as_ushort(l1) << 16) | __bfloat16_as_ushort(l0);
}
__device__ __forceinline__ void store_split2(__nv_bfloat16* hi, __nv_bfloat16* lo,
                                             size_t off, float a, float b) {
    __nv_bfloat16 h0 = __float2bfloat16_rn(a), h1 = __float2bfloat16_rn(b);
    __nv_bfloat16 l0 = __float2bfloat16_rn(a - __bfloat162float(h0));
    __nv_bfloat16 l1 = __float2bfloat16_rn(b - __bfloat162float(h1));
    *(ushort2*)(hi + off) = make_ushort2(__bfloat16_as_ushort(h0), __bfloat16_as_ushort(h1));
    *(ushort2*)(lo + off) = make_ushort2(__bfloat16_as_ushort(l0), __bfloat16_as_ushort(l1));
}
__device__ __forceinline__ float2 ld_split2(const __nv_bfloat16* hi, const __nv_bfloat16* lo,
                                            size_t off) {
    ushort2 a = *(const ushort2*)(hi + off);
    ushort2 b = *(const ushort2*)(lo + off);
    return make_float2(
        __bfloat162float(__ushort_as_bfloat16(a.x)) + __bfloat162float(__ushort_as_bfloat16(b.x)),
        __bfloat162float(__ushort_as_bfloat16(a.y)) + __bfloat162float(__ushort_as_bfloat16(b.y)));
}

// =====================================================================
// bf16x3 mma.sync GEMM, templated warp-N.
// WN=32: CTA 128x64, 4 warps @ 64x32, 3 CTAs/SM.
// WN=64: CTA 128x128, 4 warps @ 64x64, 2 CTAs/SM.
// 2-stage cp.async. C ~= Ah*Bh + Ah*Bl + Al*Bh.
// =====================================================================
#define LDA 40
#define A_MATB 10240u             // 128*LDA*2 bytes

struct GemmP {
    const __nv_bfloat16 *Ah, *Al;
    const __nv_bfloat16 *Bh[3], *Bl[3];
    const float* bias[3];
    float* Cf[3];
    __nv_bfloat16* Chi[3];
    __nv_bfloat16* Clo[3];
};

template <int WN>
__global__ __launch_bounds__(128, (WN == 32 ? 3 : 2))
void gemm_tc(GemmP gp, int N, int K, int relu) {
    extern __shared__ __align__(16) __nv_bfloat16 smem[];

    constexpr int BN   = 2 * WN;            // CTA N-tile
    constexpr int LDB  = BN + 8;            // row stride (elems), ≡16B mod 128B
    constexpr unsigned B_MATB = 32u * LDB * 2u;
    constexpr unsigned STGB   = 2u * A_MATB + 2u * B_MATB;
    constexpr int NJ = WN / 8;              // n8 blocks per warp
    constexpr int NG = WN / 16;             // ldsm n16 groups per warp
    constexpr int BCHUNK = BN / 8;          // cp16 per B row
    constexpr int BLOOP  = (32 * BCHUNK) / 128;

    const int z = blockIdx.z;
    const __nv_bfloat16* __restrict__ Ah = gp.Ah;
    const __nv_bfloat16* __restrict__ Al = gp.Al;
    const __nv_bfloat16* __restrict__ Bh = gp.Bh[z];
    const __nv_bfloat16* __restrict__ Bl = gp.Bl[z];

    const int m0 = blockIdx.y * 128;
    const int n0 = blockIdx.x * BN;
    const int t = threadIdx.x, lane = t & 31, w = t >> 5;
    const int wm = (w >> 1) * 64;
    const int wn = (w & 1) * WN;

    const unsigned sb = (unsigned)__cvta_generic_to_shared(smem);

    float acc[4][NJ][4];
#pragma unroll
    for (int i = 0; i < 4; i++)
#pragma unroll
        for (int j = 0; j < NJ; j++)
#pragma unroll
            for (int r = 0; r < 4; r++) acc[i][j][r] = 0.f;

    auto issue = [&](int S) {
        int k0 = S * 32;
        unsigned st = sb + (unsigned)((S & 1) * STGB);
#pragma unroll
        for (int j = 0; j < 4; j++) {
            int id = t + 128 * j;
            int r = id >> 2, c = (id & 3) * 8;
            cp16(st + (r * LDA + c) * 2u,          Ah + (size_t)(m0 + r) * K + k0 + c);
            cp16(st + A_MATB + (r * LDA + c) * 2u, Al + (size_t)(m0 + r) * K + k0 + c);
        }
#pragma unroll
        for (int j = 0; j < BLOOP; j++) {
            int id = t + 128 * j;
            int r = id / BCHUNK, c = (id % BCHUNK) * 8;
            cp16(st + 2 * A_MATB + (r * LDB + c) * 2u,
                 Bh + (size_t)(k0 + r) * N + n0 + c);
            cp16(st + 2 * A_MATB + B_MATB + (r * LDB + c) * 2u,
                 Bl + (size_t)(k0 + r) * N + n0 + c);
        }
        cpcommit();
    };

    const int nst = K >> 5;
    issue(0);

    for (int s = 0; s < nst; s++) {
        if (s + 1 < nst) {
            issue(s + 1);
            asm volatile("cp.async.wait_group 1;" ::: "memory");
        } else {
            asm volatile("cp.async.wait_group 0;" ::: "memory");
        }
        __syncthreads();

        unsigned st = sb + (unsigned)((s & 1) * STGB);
        unsigned a_h = st, a_l = st + A_MATB;
        unsigned b_h = st + 2 * A_MATB, b_l = b_h + B_MATB;

#pragma unroll
        for (int ks = 0; ks < 32; ks += 16) {
            unsigned ah[4][4], al[4][4];
#pragma unroll
            for (int mi = 0; mi < 4; mi++) {
                unsigned off = (unsigned)((wm + mi * 16 + (lane & 15)) * LDA
                                          + ks + (lane >> 4) * 8) * 2u;
                ldsm4(ah[mi], a_h + off);
                ldsm4(al[mi], a_l + off);
            }
            unsigned bh[NG][4], bl[NG][4];
#pragma unroll
            for (int ng = 0; ng < NG; ng++) {
                unsigned off = (unsigned)((ks + (lane & 15)) * LDB
                                          + wn + ng * 16 + (lane >> 4) * 8) * 2u;
                ldsm4t(bh[ng], b_h + off);
                ldsm4t(bl[ng], b_l + off);
            }
#pragma unroll
            for (int mi = 0; mi < 4; mi++)
#pragma unroll
                for (int nj = 0; nj < NJ; nj++) {
                    int ng = nj >> 1, p = (nj & 1) * 2;
                    mma16816(acc[mi][nj], ah[mi], bh[ng][p], bh[ng][p + 1]);
                    mma16816(acc[mi][nj], ah[mi], bl[ng][p], bl[ng][p + 1]);
                    mma16816(acc[mi][nj], al[mi], bh[ng][p], bh[ng][p + 1]);
                }
        }
        __syncthreads();
    }

    const float* __restrict__ bias = gp.bias[z];
    float* __restrict__ Cf  = gp.Cf[z];
    __nv_bfloat16* __restrict__ Chi = gp.Chi[z];
    __nv_bfloat16* __restrict__ Clo = gp.Clo[z];

#pragma unroll
    for (int mi = 0; mi < 4; mi++) {
        int row = m0 + wm + mi * 16 + (lane >> 2);
#pragma unroll
        for (int nj = 0; nj < NJ; nj++) {
            int col = n0 + wn + nj * 8 + (lane & 3) * 2;
            float b0 = bias[col], b1 = bias[col + 1];
            float v0 = acc[mi][nj][0] + b0, v1 = acc[mi][nj][1] + b1;
            float v2 = acc[mi][nj][2] + b0, v3 = acc[mi][nj][3] + b1;
            if (relu) {
                v0 = fmaxf(v0, 0.f); v1 = fmaxf(v1, 0.f);
                v2 = fmaxf(v2, 0.f); v3 = fmaxf(v3, 0.f);
            }
            if (Cf) {
                *(float2*)(Cf + (size_t)row * N + col)       = make_float2(v0, v1);
                *(float2*)(Cf + (size_t)(row + 8) * N + col) = make_float2(v2, v3);
            }
            if (Chi) {
                store_split2(Chi, Clo, (size_t)row * N + col, v0, v1);
                store_split2(Chi, Clo, (size_t)(row + 8) * N + col, v2, v3);
            }
        }
    }
}

#define SMEM_G32 (2 * (2 * 10240 + 2 * (32 * 72 * 2)))
#define SMEM_G64 (2 * (2 * 10240 + 2 * (32 * 136 * 2)))

// =====================================================================
// Attention: fast banded path (ring) + gather fallback, one kernel.
// grid = dim3(NND/64, NH), 128 threads.
// =====================================================================
#define ATT_LDS 72
#define SM_QH 0
#define SM_QL 4608
#define SM_KH 9216
#define SM_KL 16128
#define SM_VH 23040
#define SM_VL 29952
#define SM_BF 36864
#define SMEM_ATT 81920

__global__ __launch_bounds__(128, 2)
void attn_kernel(const __nv_bfloat16* __restrict__ qh, const __nv_bfloat16* __restrict__ ql,
                 const __nv_bfloat16* __restrict__ kh, const __nv_bfloat16* __restrict__ kl,
                 const __nv_bfloat16* __restrict__ vh, const __nv_bfloat16* __restrict__ vl,
                 const float* __restrict__ ebias,
                 __nv_bfloat16* __restrict__ oh, __nv_bfloat16* __restrict__ ol) {
    const unsigned FULL = 0xffffffffu;
    const int t = threadIdx.x, lane = t & 31, w = t >> 5;

    if (!g_ring) {
        // ---- fallback gather path (grid-strided) ----
        int h = w;
        int bid = blockIdx.x + gridDim.x * blockIdx.y;
        int nblocks = gridDim.x * gridDim.y;
        for (int n = bid; n < NND; n += nblocks) {
            int e   = n * DEG + lane;
            int dst = g_dst[e];
            float bias = ebias[(e << 2) + h];
            float2 q2 = ld_split2(qh, ql, (size_t)n * HID + h * HD + lane * 2);
            float myscore = 0.f;
#pragma unroll 4
            for (int j = 0; j < DEG; j++) {
                int dj = __shfl_sync(FULL, dst, j);
                float2 k2 = ld_split2(kh, kl, (size_t)dj * HID + h * HD + lane * 2);
                float p = q2.x * k2.x + q2.y * k2.y;
#pragma unroll
                for (int o = 16; o > 0; o >>= 1) p += __shfl_xor_sync(FULL, p, o);
                if (lane == j) myscore = p;
            }
            myscore = myscore * 0.125f + bias;
            float m = myscore;
#pragma unroll
            for (int o = 16; o > 0; o >>= 1) m = fmaxf(m, __shfl_xor_sync(FULL, m, o));
            float p = __expf(myscore - m);
            float s = p;
#pragma unroll
            for (int o = 16; o > 0; o >>= 1) s += __shfl_xor_sync(FULL, s, o);
            p /= s;
            float2 acc2 = make_float2(0.f, 0.f);
#pragma unroll 4
            for (int j = 0; j < DEG; j++) {
                float pj = __shfl_sync(FULL, p, j);
                int dj   = __shfl_sync(FULL, dst, j);
                float2 v2 = ld_split2(vh, vl, (size_t)dj * HID + h * HD + lane * 2);
                acc2.x += pj * v2.x;
                acc2.y += pj * v2.y;
            }
            store_split2(oh, ol, (size_t)n * HID + h * HD + lane * 2, acc2.x, acc2.y);
        }
        return;
    }

    // ---- fast banded path ----
    extern __shared__ __align__(16) ushort smu[];
    float* sB = (float*)(smu + SM_BF);
    const int h  = blockIdx.y;
    const int n0 = blockIdx.x * 64;

    for (int r = t; r < 256; r += 128) {
        const __nv_bfloat16 *sH = nullptr, *sL = nullptr;
        ushort *dH, *dL;
        if (r < 64) {
            int node = n0 + r;
            sH = qh + (size_t)node * HID + h * HD;
            sL = ql + (size_t)node * HID + h * HD;
            dH = smu + SM_QH + r * ATT_LDS; dL = smu + SM_QL + r * ATT_LDS;
        } else if (r < 160) {
            int i = r - 64;
            dH = smu + SM_KH + i * ATT_LDS; dL = smu + SM_KL + i * ATT_LDS;
            if (i < 95) {
                int node = (n0 + 1 + i) & (NND - 1);
                sH = kh + (size_t)node * HID + h * HD;
                sL = kl + (size_t)node * HID + h * HD;
            }
        } else {
            int i = r - 160;
            dH = smu + SM_VH + i * ATT_LDS; dL = smu + SM_VL + i * ATT_LDS;
            if (i < 95) {
                int node = (n0 + 1 + i) & (NND - 1);
                sH = vh + (size_t)node * HID + h * HD;
                sL = vl + (size_t)node * HID + h * HD;
            }
        }
        if (sH) {
#pragma unroll
            for (int j2 = 0; j2 < 8; j2++) {
                ((uint4*)dH)[j2] = ((const uint4*)sH)[j2];
                ((uint4*)dL)[j2] = ((const uint4*)sL)[j2];
            }
        } else {
            uint4 z4 = make_uint4(0, 0, 0, 0);
#pragma unroll
            for (int j2 = 0; j2 < 8; j2++) { ((uint4*)dH)[j2] = z4; ((uint4*)dL)[j2] = z4; }
        }
    }
    for (int i = t; i < 2048; i += 128)
        sB[i] = ebias[(((size_t)(n0 * DEG + i)) << 2) + h];
    __syncthreads();

    const unsigned base = (unsigned)__cvta_generic_to_shared(smu);
    const unsigned aQh = base + SM_QH * 2u, aQl = base + SM_QL * 2u;
    const unsigned aKh = base + SM_KH * 2u, aKl = base + SM_KL * 2u;
    const unsigned aVh = base + SM_VH * 2u, aVl = base + SM_VL * 2u;

    unsigned qah[4][4], qal[4][4];
#pragma unroll
    for (int kk = 0; kk < 4; kk++) {
        unsigned off = (unsigned)((16 * w + (lane & 15)) * ATT_LDS + kk * 16 + (lane >> 4) * 8) * 2u;
        ldsm4(qah[kk], aQh + off);
        ldsm4(qal[kk], aQl + off);
    }

    float acc[6][4];
#pragma unroll
    for (int i = 0; i < 6; i++)
#pragma unroll
        for (int c = 0; c < 4; c++) acc[i][c] = 0.f;

    const int g2 = lane >> 3, lr = lane & 7;
#pragma unroll
    for (int nb2 = 0; nb2 < 3; nb2++) {
        int n16 = 16 * w + nb2 * 16;
#pragma unroll
        for (int kk = 0; kk < 4; kk++) {
            unsigned kbh[4], kbl[4];
            unsigned off = (unsigned)((n16 + lr + (g2 >> 1) * 8) * ATT_LDS
                                      + kk * 16 + (g2 & 1) * 8) * 2u;
            ldsm4(kbh, aKh + off);
            ldsm4(kbl, aKl + off);
            mma16816(acc[2 * nb2],     qah[kk], kbh[0], kbh[1]);
            mma16816(acc[2 * nb2],     qah[kk], kbl[0], kbl[1]);
            mma16816(acc[2 * nb2],     qal[kk], kbh[0], kbh[1]);
            mma16816(acc[2 * nb2 + 1], qah[kk], kbh[2], kbh[3]);
            mma16816(acc[2 * nb2 + 1], qah[kk], kbl[2], kbl[3]);
            mma16816(acc[2 * nb2 + 1], qal[kk], kbh[2], kbh[3]);
        }
    }

    const int q4 = lane >> 2, c2 = 2 * (lane & 3);
    float mlo = -1e30f, mhi = -1e30f;
#pragma unroll
    for (int nb = 0; nb < 6; nb++) {
#pragma unroll
        for (int c = 0; c < 4; c++) {
            int rofs = q4 + (c >> 1) * 8;
            int j = 8 * nb + c2 + (c & 1) - rofs;
            int rloc = 16 * w + rofs;
            float sc = ((unsigned)j < 32u)
                           ? acc[nb][c] * 0.125f + sB[rloc * DEG + j]
                           : -1e30f;
            acc[nb][c] = sc;
            if (c < 2) mlo = fmaxf(mlo, sc); else mhi = fmaxf(mhi, sc);
        }
    }
#pragma unroll
    for (int o = 1; o <= 2; o <<= 1) {
        mlo = fmaxf(mlo, __shfl_xor_sync(FULL, mlo, o));
        mhi = fmaxf(mhi, __shfl_xor_sync(FULL, mhi, o));
    }
    float slo = 0.f, shi = 0.f;
#pragma unroll
    for (int nb = 0; nb < 6; nb++) {
#pragma unroll
        for (int c = 0; c < 4; c++) {
            float p = __expf(acc[nb][c] - ((c < 2) ? mlo : mhi));
            acc[nb][c] = p;
            if (c < 2) slo += p; else shi += p;
        }
    }
#pragma unroll
    for (int o = 1; o <= 2; o <<= 1) {
        slo += __shfl_xor_sync(FULL, slo, o);
        shi += __shfl_xor_sync(FULL, shi, o);
    }
    float ilo = 1.f / slo, ihi = 1.f / shi;
#pragma unroll
    for (int nb = 0; nb < 6; nb++) {
        acc[nb][0] *= ilo; acc[nb][1] *= ilo;
        acc[nb][2] *= ihi; acc[nb][3] *= ihi;
    }

    float oacc[8][4];
#pragma unroll
    for (int i = 0; i < 8; i++)
#pragma unroll
        for (int c = 0; c < 4; c++) oacc[i][c] = 0.f;

#pragma unroll
    for (int t3 = 0; t3 < 3; t3++) {
        unsigned pah[4], pal[4];
        split_pack(acc[2 * t3][0],     acc[2 * t3][1],     pah[0], pal[0]);
        split_pack(acc[2 * t3][2],     acc[2 * t3][3],     pah[1], pal[1]);
        split_pack(acc[2 * t3 + 1][0], acc[2 * t3 + 1][1], pah[2], pal[2]);
        split_pack(acc[2 * t3 + 1][2], acc[2 * t3 + 1][3], pah[3], pal[3]);
#pragma unroll
        for (int ng = 0; ng < 4; ng++) {
            unsigned vbh[4], vbl[4];
            unsigned off = (unsigned)((16 * w + 16 * t3 + (lane & 15)) * ATT_LDS
                                      + ng * 16 + (lane >> 4) * 8) * 2u;
            ldsm4t(vbh, aVh + off);
            ldsm4t(vbl, aVl + off);
            mma16816(oacc[2 * ng],     pah, vbh[0], vbh[1]);
            mma16816(oacc[2 * ng],     pah, vbl[0], vbl[1]);
            mma16816(oacc[2 * ng],     pal, vbh[0], vbh[1]);
            mma16816(oacc[2 * ng + 1], pah, vbh[2], vbh[3]);
            mma16816(oacc[2 * ng + 1], pah, vbl[2], vbl[3]);
            mma16816(oacc[2 * ng + 1], pal, vbh[2], vbh[3]);
        }
    }

    int row0 = n0 + 16 * w + q4;
#pragma unroll
    for (int idx = 0; idx < 8; idx++) {
        int col = h * HD + (idx >> 1) * 16 + (idx & 1) * 8 + c2;
        store_split2(oh, ol, (size_t)row0 * HID + col,       oacc[idx][0], oacc[idx][1]);
        store_split2(oh, ol, (size_t)(row0 + 8) * HID + col, oacc[idx][2], oacc[idx][3]);
    }
}

// ---------------- fused residual add + LayerNorm ----------------
__global__ __launch_bounds__(256)
void add_ln_kernel(const float* __restrict__ a, const float* __restrict__ b,
                   const float* __restrict__ g, const float* __restrict__ be,
                   float* __restrict__ out,
                   __nv_bfloat16* __restrict__ ohi, __nv_bfloat16* __restrict__ olo) {
    const unsigned FULL = 0xffffffffu;
    int row  = blockIdx.x * (blockDim.x >> 5) + (threadIdx.x >> 5);
    int lane = threadIdx.x & 31;
    const float* ra = a + (size_t)row * HID;
    const float* rb = b + (size_t)row * HID;

    float vals[8];
    float s = 0.f;
#pragma unroll
    for (int i = 0; i < 8; i++) {
        float v = ra[lane + i * 32] + rb[lane + i * 32];
        vals[i] = v;
        s += v;
    }
#pragma unroll
    for (int o = 16; o > 0; o >>= 1) s += __shfl_xor_sync(FULL, s, o);
    float mean = s * (1.f / HID);

    float var = 0.f;
#pragma unroll
    for (int i = 0; i < 8; i++) {
        float d = vals[i] - mean;
        var += d * d;
    }
#pragma unroll
    for (int o = 16; o > 0; o >>= 1) var += __shfl_xor_sync(FULL, var, o);
    var *= (1.f / HID);
    float inv = rsqrtf(var + 1e-5f);

#pragma unroll
    for (int i = 0; i < 8; i++) {
        int c = lane + i * 32;
        float v = (vals[i] - mean) * inv * g[c] + be[c];
        out[(size_t)row * HID + c] = v;
        if (ohi) {
            __nv_bfloat16 hh = __float2bfloat16_rn(v);
            __nv_bfloat16 ll = __float2bfloat16_rn(v - __bfloat162float(hh));
            ohi[(size_t)row * HID + c] = hh;
            olo[(size_t)row * HID + c] = ll;
        }
    }
}

// ---------------- launch ----------------
extern "C" void kernel_launch(void* const* d_in, const int* in_sizes, int n_in,
                              void* d_out, int out_size) {
    const float* x          = (const float*)d_in[0];
    const int*   edge_index = (const int*)d_in[1];
    const float* edge_attr  = (const float*)d_in[2];
    const float* Wq  = (const float*)d_in[3];
    const float* bq  = (const float*)d_in[4];
    const float* Wk  = (const float*)d_in[5];
    const float* bk  = (const float*)d_in[6];
    const float* Wv  = (const float*)d_in[7];
    const float* bv  = (const float*)d_in[8];
    const float* Wo  = (const float*)d_in[9];
    const float* bo  = (const float*)d_in[10];
    const float* We  = (const float*)d_in[11];
    const float* be  = (const float*)d_in[12];
    const float* g1  = (const float*)d_in[13];
    const float* b1  = (const float*)d_in[14];
    const float* g2  = (const float*)d_in[15];
    const float* b2  = (const float*)d_in[16];
    const float* Wf1 = (const float*)d_in[17];
    const float* bf1 = (const float*)d_in[18];
    const float* Wf2 = (const float*)d_in[19];
    const float* bf2 = (const float*)d_in[20];
    float* out = (float*)d_out;

    float *tmp, *x1, *ebias;
    __nv_bfloat16 *xh, *xl, *wh, *wl, *ah, *al, *x1h, *x1l, *h1h, *h1l;
    __nv_bfloat16 *qh, *ql, *kh, *kl, *vh, *vl;
    cudaGetSymbolAddress((void**)&tmp,   g_tmp);
    cudaGetSymbolAddress((void**)&x1,    g_x1);
    cudaGetSymbolAddress((void**)&ebias, g_ebias);
    cudaGetSymbolAddress((void**)&xh,  g_xh);   cudaGetSymbolAddress((void**)&xl,  g_xl);
    cudaGetSymbolAddress((void**)&wh,  g_wh);   cudaGetSymbolAddress((void**)&wl,  g_wl);
    cudaGetSymbolAddress((void**)&qh,  g_qh);   cudaGetSymbolAddress((void**)&ql,  g_ql);
    cudaGetSymbolAddress((void**)&kh,  g_kh);   cudaGetSymbolAddress((void**)&kl,  g_kl);
    cudaGetSymbolAddress((void**)&vh,  g_vh);   cudaGetSymbolAddress((void**)&vl,  g_vl);
    cudaGetSymbolAddress((void**)&ah,  g_ah);   cudaGetSymbolAddress((void**)&al,  g_al);
    cudaGetSymbolAddress((void**)&x1h, g_x1h);  cudaGetSymbolAddress((void**)&x1l, g_x1l);
    cudaGetSymbolAddress((void**)&h1h, g_h1h);  cudaGetSymbolAddress((void**)&h1l, g_h1l);

    cudaFuncSetAttribute(gemm_tc<32>,  cudaFuncAttributeMaxDynamicSharedMemorySize, SMEM_G32);
    cudaFuncSetAttribute(gemm_tc<64>,  cudaFuncAttributeMaxDynamicSharedMemorySize, SMEM_G64);
    cudaFuncSetAttribute(attn_kernel,  cudaFuncAttributeMaxDynamicSharedMemorySize, SMEM_ATT);

    PrepP pp;
    pp.j[0] = {x,   xh,           xl,           NND * HID / 4};
    pp.j[1] = {Wq,  wh + WOFF_Q,  wl + WOFF_Q,  HID * HID / 4};
    pp.j[2] = {Wk,  wh + WOFF_K,  wl + WOFF_K,  HID * HID / 4};
    pp.j[3] = {Wv,  wh + WOFF_V,  wl + WOFF_V,  HID * HID / 4};
    pp.j[4] = {Wo,  wh + WOFF_O,  wl + WOFF_O,  HID * HID / 4};
    pp.j[5] = {Wf1, wh + WOFF_F1, wl + WOFF_F1, HID * FFN / 4};
    pp.j[6] = {Wf2, wh + WOFF_F2, wl + WOFF_F2, FFN * HID / 4};
    pp.words = edge_index;
    pp.ea = edge_attr; pp.We = We; pp.be = be; pp.ebias = ebias;
    prep_all<<<dim3(192, 9), 256>>>(pp);

    // QKV (z-batched): WN=64, grid 2x32x3 = 192 CTAs
    GemmP pqkv = {};
    pqkv.Ah = xh; pqkv.Al = xl;
    pqkv.Bh[0] = wh + WOFF_Q; pqkv.Bl[0] = wl + WOFF_Q;
    pqkv.Bh[1] = wh + WOFF_K; pqkv.Bl[1] = wl + WOFF_K;
    pqkv.Bh[2] = wh + WOFF_V; pqkv.Bl[2] = wl + WOFF_V;
    pqkv.bias[0] = bq; pqkv.bias[1] = bk; pqkv.bias[2] = bv;
    pqkv.Chi[0] = qh; pqkv.Chi[1] = kh; pqkv.Chi[2] = vh;
    pqkv.Clo[0] = ql; pqkv.Clo[1] = kl; pqkv.Clo[2] = vl;
    gemm_tc<64><<<dim3(HID / 128, NND / 128, 3), 128, SMEM_G64>>>(pqkv, HID, HID, 0);

    attn_kernel<<<dim3(NND / 64, NH), 128, SMEM_ATT>>>(qh, ql, kh, kl, vh, vl, ebias, ah, al);

    // O projection: WN=32, grid 4x32 = 128 CTAs
    GemmP po = {};
    po.Ah = ah; po.Al = al;
    po.Bh[0] = wh + WOFF_O; po.Bl[0] = wl + WOFF_O;
    po.bias[0] = bo;
    po.Cf[0] = tmp;
    gemm_tc<32><<<dim3(HID / 64, NND / 128, 1), 128, SMEM_G32>>>(po, HID, HID, 0);

    add_ln_kernel<<<NND / 8, 256>>>(x, tmp, g1, b1, x1, x1h, x1l);

    // FFN1: WN=64, grid 8x32 = 256 CTAs
    GemmP pf1 = {};
    pf1.Ah = x1h; pf1.Al = x1l;
    pf1.Bh[0] = wh + WOFF_F1; pf1.Bl[0] = wl + WOFF_F1;
    pf1.bias[0] = bf1;
    pf1.Chi[0] = h1h; pf1.Clo[0] = h1l;
    gemm_tc<64><<<dim3(FFN / 128, NND / 128, 1), 128, SMEM_G64>>>(pf1, FFN, HID, 1);

    // FFN2: WN=32, grid 4x32 = 128 CTAs
    GemmP pf2 = {};
    pf2.Ah = h1h; pf2.Al = h1l;
    pf2.Bh[0] = wh + WOFF_F2; pf2.Bl[0] = wl + WOFF_F2;
    pf2.bias[0] = bf2;
    pf2.Cf[0] = tmp;
    gemm_tc<32><<<dim3(HID / 64, NND / 128, 1), 128, SMEM_G32>>>(pf2, HID, FFN, 0);

    add_ln_kernel<<<NND / 8, 256>>>(x1, tmp, g2, b2, out, nullptr, nullptr);
}

// round 11
// speedup vs baseline: 1.0016x; 1.0016x over previous
#include <cuda_runtime.h>
#include <cuda_bf16.h>
#include <cstdint>
#include <math.h>

#define NND   4096
#define HID   256
#define NH    4
#define HD    64
#define DEG   32
#define NE    (NND * DEG)
#define EDIM  16
#define FFN   1024

#define WOFF_Q  0
#define WOFF_K  65536
#define WOFF_V  131072
#define WOFF_O  196608
#define WOFF_F1 262144
#define WOFF_F2 524288

// ---------------- scratch ----------------
__device__ float g_tmp[NND * HID];
__device__ float g_x1[NND * HID];
__device__ int   g_dst[NE];
__device__ int   g_ring = 1;
__device__ float g_ebias[NE * 4];

__device__ __nv_bfloat16 g_xh[NND * HID],  g_xl[NND * HID];
__device__ __nv_bfloat16 g_wh[786432],     g_wl[786432];
__device__ __nv_bfloat16 g_qh[NND * HID],  g_ql[NND * HID];
__device__ __nv_bfloat16 g_kh[NND * HID],  g_kl[NND * HID];
__device__ __nv_bfloat16 g_vh[NND * HID],  g_vl[NND * HID];
__device__ __nv_bfloat16 g_ah[NND * HID],  g_al[NND * HID];
__device__ __nv_bfloat16 g_x1h[NND * HID], g_x1l[NND * HID];
__device__ __nv_bfloat16 g_h1h[NND * FFN], g_h1l[NND * FFN];

// ---------------- merged prep: splits + edge decode + edge bias ----------------
struct SplitJob { const float* src; __nv_bfloat16* hi; __nv_bfloat16* lo; int n4; };
struct PrepP {
    SplitJob j[7];
    const int* words;
    const float *ea, *We, *be;
    float* ebias;
};

__global__ __launch_bounds__(256)
void prep_all(PrepP p) {
    int job = blockIdx.y;
    int stride = gridDim.x * blockDim.x;
    if (job < 7) {
        SplitJob jb = p.j[job];
        for (int i = blockIdx.x * blockDim.x + threadIdx.x; i < jb.n4; i += stride) {
            float4 v = ((const float4*)jb.src)[i];
            float f[4] = {v.x, v.y, v.z, v.w};
            __nv_bfloat16 h[4], l[4];
#pragma unroll
            for (int k = 0; k < 4; k++) {
                h[k] = __float2bfloat16_rn(f[k]);
                l[k] = __float2bfloat16_rn(f[k] - __bfloat162float(h[k]));
            }
            ((ushort4*)jb.hi)[i] = make_ushort4(
                __bfloat16_as_ushort(h[0]), __bfloat16_as_ushort(h[1]),
                __bfloat16_as_ushort(h[2]), __bfloat16_as_ushort(h[3]));
            ((ushort4*)jb.lo)[i] = make_ushort4(
                __bfloat16_as_ushort(l[0]), __bfloat16_as_ushort(l[1]),
                __bfloat16_as_ushort(l[2]), __bfloat16_as_ushort(l[3]));
        }
    } else if (job == 7) {
        for (int e = blockIdx.x * blockDim.x + threadIdx.x; e < NE; e += stride) {
            bool is32 = (p.words[32] == 1);
            int dst = is32 ? p.words[NE + e] : p.words[2 * NE + 2 * e];
            g_dst[e] = dst;
            int expect = ((e / DEG) + 1 + (e % DEG)) & (NND - 1);
            if (dst != expect) g_ring = 0;
        }
    } else {
        for (int e = blockIdx.x * blockDim.x + threadIdx.x; e < NE; e += stride) {
            float a0 = p.be[0], a1 = p.be[1], a2 = p.be[2], a3 = p.be[3];
            const float4* q = (const float4*)(p.ea + (size_t)e * EDIM);
#pragma unroll
            for (int c4 = 0; c4 < 4; c4++) {
                float4 x4 = q[c4];
                float xs[4] = {x4.x, x4.y, x4.z, x4.w};
#pragma unroll
                for (int i = 0; i < 4; i++) {
                    int c = c4 * 4 + i;
                    a0 += xs[i] * p.We[c * NH + 0];
                    a1 += xs[i] * p.We[c * NH + 1];
                    a2 += xs[i] * p.We[c * NH + 2];
                    a3 += xs[i] * p.We[c * NH + 3];
                }
            }
            ((float4*)p.ebias)[e] = make_float4(a0, a1, a2, a3);
        }
    }
}

// ---------------- helpers ----------------
__device__ __forceinline__ void cp16(unsigned dst, const void* src) {
    asm volatile("cp.async.cg.shared.global [%0], [%1], 16;" :: "r"(dst), "l"(src));
}
__device__ __forceinline__ void cpcommit() { asm volatile("cp.async.commit_group;"); }
__device__ __forceinline__ void ldsm4(unsigned r[4], unsigned addr) {
    asm volatile("ldmatrix.sync.aligned.m8n8.x4.shared.b16 {%0,%1,%2,%3}, [%4];"
                 : "=r"(r[0]), "=r"(r[1]), "=r"(r[2]), "=r"(r[3]) : "r"(addr));
}
__device__ __forceinline__ void ldsm4t(unsigned r[4], unsigned addr) {
    asm volatile("ldmatrix.sync.aligned.m8n8.x4.trans.shared.b16 {%0,%1,%2,%3}, [%4];"
                 : "=r"(r[0]), "=r"(r[1]), "=r"(r[2]), "=r"(r[3]) : "r"(addr));
}
__device__ __forceinline__ void mma16816(float c[4], const unsigned a[4],
                                         const unsigned b0, const unsigned b1) {
    asm volatile(
        "mma.sync.aligned.m16n8k16.row.col.f32.bf16.bf16.f32 "
        "{%0,%1,%2,%3}, {%4,%5,%6,%7}, {%8,%9}, {%0,%1,%2,%3};"
        : "+f"(c[0]), "+f"(c[1]), "+f"(c[2]), "+f"(c[3])
        : "r"(a[0]), "r"(a[1]), "r"(a[2]), "r"(a[3]), "r"(b0), "r"(b1));
}
__device__ __forceinline__ void split_pack(float v0, float v1,
                                           unsigned& hi, unsigned& lo) {
    __nv_bfloat16 h0 = __float2bfloat16_rn(v0);
    __nv_bfloat16 h1 = __float2bfloat16_rn(v1);
    __nv_bfloat16 l0 = __float2bfloat16_rn(v0 - __bfloat162float(h0));
    __nv_bfloat16 l1 = __float2bfloat16_rn(v1 - __bfloat162float(h1));
    hi = ((unsigned)__bfloat16_as_ushort(h1) << 16) | __bfloat16_as_ushort(h0);
    lo = ((unsigned)__bfloat16_as_ushort(l1) << 16) | __bfloat16_as_ushort(l0);
}
__device__ __forceinline__ void store_split2(__nv_bfloat16* hi, __nv_bfloat16* lo,
                                             size_t off, float a, float b) {
    __nv_bfloat16 h0 = __float2bfloat16_rn(a), h1 = __float2bfloat16_rn(b);
    __nv_bfloat16 l0 = __float2bfloat16_rn(a - __bfloat162float(h0));
    __nv_bfloat16 l1 = __float2bfloat16_rn(b - __bfloat162float(h1));
    *(ushort2*)(hi + off) = make_ushort2(__bfloat16_as_ushort(h0), __bfloat16_as_ushort(h1));
    *(ushort2*)(lo + off) = make_ushort2(__bfloat16_as_ushort(l0), __bfloat16_as_ushort(l1));
}
__device__ __forceinline__ float2 ld_split2(const __nv_bfloat16* hi, const __nv_bfloat16* lo,
                                            size_t off) {
    ushort2 a = *(const ushort2*)(hi + off);
    ushort2 b = *(const ushort2*)(lo + off);
    return make_float2(
        __bfloat162float(__ushort_as_bfloat16(a.x)) + __bfloat162float(__ushort_as_bfloat16(b.x)),
        __bfloat162float(__ushort_as_bfloat16(a.y)) + __bfloat162float(__ushort_as_bfloat16(b.y)));
}

// =====================================================================
// bf16x3 mma.sync GEMM, templated warp-N.
// WN=32: CTA 128x64, 4 warps @ 64x32, 3 CTAs/SM.
// WN=64: CTA 128x128, 4 warps @ 64x64, 2 CTAs/SM.
// 2-stage cp.async. C ~= Ah*Bh + Ah*Bl + Al*Bh.
// =====================================================================
#define LDA 40
#define A_MATB 10240u             // 128*LDA*2 bytes

struct GemmP {
    const __nv_bfloat16 *Ah, *Al;
    const __nv_bfloat16 *Bh[3], *Bl[3];
    const float* bias[3];
    float* Cf[3];
    __nv_bfloat16* Chi[3];
    __nv_bfloat16* Clo[3];
};

template <int WN>
__global__ __launch_bounds__(128, (WN == 32 ? 3 : 2))
void gemm_tc(GemmP gp, int N, int K, int relu) {
    extern __shared__ __align__(16) __nv_bfloat16 smem[];

    constexpr int BN   = 2 * WN;            // CTA N-tile
    constexpr int LDB  = BN + 8;            // row stride (elems), ≡16B mod 128B
    constexpr unsigned B_MATB = 32u * LDB * 2u;
    constexpr unsigned STGB   = 2u * A_MATB + 2u * B_MATB;
    constexpr int NJ = WN / 8;              // n8 blocks per warp
    constexpr int NG = WN / 16;             // ldsm n16 groups per warp
    constexpr int BCHUNK = BN / 8;          // cp16 per B row
    constexpr int BLOOP  = (32 * BCHUNK) / 128;

    const int z = blockIdx.z;
    const __nv_bfloat16* __restrict__ Ah = gp.Ah;
    const __nv_bfloat16* __restrict__ Al = gp.Al;
    const __nv_bfloat16* __restrict__ Bh = gp.Bh[z];
    const __nv_bfloat16* __restrict__ Bl = gp.Bl[z];

    const int m0 = blockIdx.y * 128;
    const int n0 = blockIdx.x * BN;
    const int t = threadIdx.x, lane = t & 31, w = t >> 5;
    const int wm = (w >> 1) * 64;
    const int wn = (w & 1) * WN;

    const unsigned sb = (unsigned)__cvta_generic_to_shared(smem);

    float acc[4][NJ][4];
#pragma unroll
    for (int i = 0; i < 4; i++)
#pragma unroll
        for (int j = 0; j < NJ; j++)
#pragma unroll
            for (int r = 0; r < 4; r++) acc[i][j][r] = 0.f;

    auto issue = [&](int S) {
        int k0 = S * 32;
        unsigned st = sb + (unsigned)((S & 1) * STGB);
#pragma unroll
        for (int j = 0; j < 4; j++) {
            int id = t + 128 * j;
            int r = id >> 2, c = (id & 3) * 8;
            cp16(st + (r * LDA + c) * 2u,          Ah + (size_t)(m0 + r) * K + k0 + c);
            cp16(st + A_MATB + (r * LDA + c) * 2u, Al + (size_t)(m0 + r) * K + k0 + c);
        }
#pragma unroll
        for (int j = 0; j < BLOOP; j++) {
            int id = t + 128 * j;
            int r = id / BCHUNK, c = (id % BCHUNK) * 8;
            cp16(st + 2 * A_MATB + (r * LDB + c) * 2u,
                 Bh + (size_t)(k0 + r) * N + n0 + c);
            cp16(st + 2 * A_MATB + B_MATB + (r * LDB + c) * 2u,
                 Bl + (size_t)(k0 + r) * N + n0 + c);
        }
        cpcommit();
    };

    const int nst = K >> 5;
    issue(0);

    for (int s = 0; s < nst; s++) {
        if (s + 1 < nst) {
            issue(s + 1);
            asm volatile("cp.async.wait_group 1;" ::: "memory");
        } else {
            asm volatile("cp.async.wait_group 0;" ::: "memory");
        }
        __syncthreads();

        unsigned st = sb + (unsigned)((s & 1) * STGB);
        unsigned a_h = st, a_l = st + A_MATB;
        unsigned b_h = st + 2 * A_MATB, b_l = b_h + B_MATB;

#pragma unroll
        for (int ks = 0; ks < 32; ks += 16) {
            unsigned ah[4][4], al[4][4];
#pragma unroll
            for (int mi = 0; mi < 4; mi++) {
                unsigned off = (unsigned)((wm + mi * 16 + (lane & 15)) * LDA
                                          + ks + (lane >> 4) * 8) * 2u;
                ldsm4(ah[mi], a_h + off);
                ldsm4(al[mi], a_l + off);
            }
            unsigned bh[NG][4], bl[NG][4];
#pragma unroll
            for (int ng = 0; ng < NG; ng++) {
                unsigned off = (unsigned)((ks + (lane & 15)) * LDB
                                          + wn + ng * 16 + (lane >> 4) * 8) * 2u;
                ldsm4t(bh[ng], b_h + off);
                ldsm4t(bl[ng], b_l + off);
            }
#pragma unroll
            for (int mi = 0; mi < 4; mi++)
#pragma unroll
                for (int nj = 0; nj < NJ; nj++) {
                    int ng = nj >> 1, p = (nj & 1) * 2;
                    mma16816(acc[mi][nj], ah[mi], bh[ng][p], bh[ng][p + 1]);
                    mma16816(acc[mi][nj], ah[mi], bl[ng][p], bl[ng][p + 1]);
                    mma16816(acc[mi][nj], al[mi], bh[ng][p], bh[ng][p + 1]);
                }
        }
        __syncthreads();
    }

    const float* __restrict__ bias = gp.bias[z];
    float* __restrict__ Cf  = gp.Cf[z];
    __nv_bfloat16* __restrict__ Chi = gp.Chi[z];
    __nv_bfloat16* __restrict__ Clo = gp.Clo[z];

#pragma unroll
    for (int mi = 0; mi < 4; mi++) {
        int row = m0 + wm + mi * 16 + (lane >> 2);
#pragma unroll
        for (int nj = 0; nj < NJ; nj++) {
            int col = n0 + wn + nj * 8 + (lane & 3) * 2;
            float b0 = bias[col], b1 = bias[col + 1];
            float v0 = acc[mi][nj][0] + b0, v1 = acc[mi][nj][1] + b1;
            float v2 = acc[mi][nj][2] + b0, v3 = acc[mi][nj][3] + b1;
            if (relu) {
                v0 = fmaxf(v0, 0.f); v1 = fmaxf(v1, 0.f);
                v2 = fmaxf(v2, 0.f); v3 = fmaxf(v3, 0.f);
            }
            if (Cf) {
                *(float2*)(Cf + (size_t)row * N + col)       = make_float2(v0, v1);
                *(float2*)(Cf + (size_t)(row + 8) * N + col) = make_float2(v2, v3);
            }
            if (Chi) {
                store_split2(Chi, Clo, (size_t)row * N + col, v0, v1);
                store_split2(Chi, Clo, (size_t)(row + 8) * N + col, v2, v3);
            }
        }
    }
}

#define SMEM_G32 (2 * (2 * 10240 + 2 * (32 * 72 * 2)))
#define SMEM_G64 (2 * (2 * 10240 + 2 * (32 * 136 * 2)))

// =====================================================================
// Attention: fast banded path (ring) + gather fallback, one kernel.
// grid = dim3(NND/64, NH), 128 threads.
// =====================================================================
#define ATT_LDS 72
#define SM_QH 0
#define SM_QL 4608
#define SM_KH 9216
#define SM_KL 16128
#define SM_VH 23040
#define SM_VL 29952
#define SM_BF 36864
#define SMEM_ATT 81920

__global__ __launch_bounds__(128, 2)
void attn_kernel(const __nv_bfloat16* __restrict__ qh, const __nv_bfloat16* __restrict__ ql,
                 const __nv_bfloat16* __restrict__ kh, const __nv_bfloat16* __restrict__ kl,
                 const __nv_bfloat16* __restrict__ vh, const __nv_bfloat16* __restrict__ vl,
                 const float* __restrict__ ebias,
                 __nv_bfloat16* __restrict__ oh, __nv_bfloat16* __restrict__ ol) {
    const unsigned FULL = 0xffffffffu;
    const int t = threadIdx.x, lane = t & 31, w = t >> 5;

    if (!g_ring) {
        // ---- fallback gather path (grid-strided) ----
        int h = w;
        int bid = blockIdx.x + gridDim.x * blockIdx.y;
        int nblocks = gridDim.x * gridDim.y;
        for (int n = bid; n < NND; n += nblocks) {
            int e   = n * DEG + lane;
            int dst = g_dst[e];
            float bias = ebias[(e << 2) + h];
            float2 q2 = ld_split2(qh, ql, (size_t)n * HID + h * HD + lane * 2);
            float myscore = 0.f;
#pragma unroll 4
            for (int j = 0; j < DEG; j++) {
                int dj = __shfl_sync(FULL, dst, j);
                float2 k2 = ld_split2(kh, kl, (size_t)dj * HID + h * HD + lane * 2);
                float p = q2.x * k2.x + q2.y * k2.y;
#pragma unroll
                for (int o = 16; o > 0; o >>= 1) p += __shfl_xor_sync(FULL, p, o);
                if (lane == j) myscore = p;
            }
            myscore = myscore * 0.125f + bias;
            float m = myscore;
#pragma unroll
            for (int o = 16; o > 0; o >>= 1) m = fmaxf(m, __shfl_xor_sync(FULL, m, o));
            float p = __expf(myscore - m);
            float s = p;
#pragma unroll
            for (int o = 16; o > 0; o >>= 1) s += __shfl_xor_sync(FULL, s, o);
            p /= s;
            float2 acc2 = make_float2(0.f, 0.f);
#pragma unroll 4
            for (int j = 0; j < DEG; j++) {
                float pj = __shfl_sync(FULL, p, j);
                int dj   = __shfl_sync(FULL, dst, j);
                float2 v2 = ld_split2(vh, vl, (size_t)dj * HID + h * HD + lane * 2);
                acc2.x += pj * v2.x;
                acc2.y += pj * v2.y;
            }
            store_split2(oh, ol, (size_t)n * HID + h * HD + lane * 2, acc2.x, acc2.y);
        }
        return;
    }

    // ---- fast banded path ----
    extern __shared__ __align__(16) ushort smu[];
    float* sB = (float*)(smu + SM_BF);
    const int h  = blockIdx.y;
    const int n0 = blockIdx.x * 64;

    for (int r = t; r < 256; r += 128) {
        const __nv_bfloat16 *sH = nullptr, *sL = nullptr;
        ushort *dH, *dL;
        if (r < 64) {
            int node = n0 + r;
            sH = qh + (size_t)node * HID + h * HD;
            sL = ql + (size_t)node * HID + h * HD;
            dH = smu + SM_QH + r * ATT_LDS; dL = smu + SM_QL + r * ATT_LDS;
        } else if (r < 160) {
            int i = r - 64;
            dH = smu + SM_KH + i * ATT_LDS; dL = smu + SM_KL + i * ATT_LDS;
            if (i < 95) {
                int node = (n0 + 1 + i) & (NND - 1);
                sH = kh + (size_t)node * HID + h * HD;
                sL = kl + (size_t)node * HID + h * HD;
            }
        } else {
            int i = r - 160;
            dH = smu + SM_VH + i * ATT_LDS; dL = smu + SM_VL + i * ATT_LDS;
            if (i < 95) {
                int node = (n0 + 1 + i) & (NND - 1);
                sH = vh + (size_t)node * HID + h * HD;
                sL = vl + (size_t)node * HID + h * HD;
            }
        }
        if (sH) {
#pragma unroll
            for (int j2 = 0; j2 < 8; j2++) {
                ((uint4*)dH)[j2] = ((const uint4*)sH)[j2];
                ((uint4*)dL)[j2] = ((const uint4*)sL)[j2];
            }
        } else {
            uint4 z4 = make_uint4(0, 0, 0, 0);
#pragma unroll
            for (int j2 = 0; j2 < 8; j2++) { ((uint4*)dH)[j2] = z4; ((uint4*)dL)[j2] = z4; }
        }
    }
    for (int i = t; i < 2048; i += 128)
        sB[i] = ebias[(((size_t)(n0 * DEG + i)) << 2) + h];
    __syncthreads();

    const unsigned base = (unsigned)__cvta_generic_to_shared(smu);
    const unsigned aQh = base + SM_QH * 2u, aQl = base + SM_QL * 2u;
    const unsigned aKh = base + SM_KH * 2u, aKl = base + SM_KL * 2u;
    const unsigned aVh = base + SM_VH * 2u, aVl = base + SM_VL * 2u;

    unsigned qah[4][4], qal[4][4];
#pragma unroll
    for (int kk = 0; kk < 4; kk++) {
        unsigned off = (unsigned)((16 * w + (lane & 15)) * ATT_LDS + kk * 16 + (lane >> 4) * 8) * 2u;
        ldsm4(qah[kk], aQh + off);
        ldsm4(qal[kk], aQl + off);
    }

    float acc[6][4];
#pragma unroll
    for (int i = 0; i < 6; i++)
#pragma unroll
        for (int c = 0; c < 4; c++) acc[i][c] = 0.f;

    const int g2 = lane >> 3, lr = lane & 7;
#pragma unroll
    for (int nb2 = 0; nb2 < 3; nb2++) {
        int n16 = 16 * w + nb2 * 16;
#pragma unroll
        for (int kk = 0; kk < 4; kk++) {
            unsigned kbh[4], kbl[4];
            unsigned off = (unsigned)((n16 + lr + (g2 >> 1) * 8) * ATT_LDS
                                      + kk * 16 + (g2 & 1) * 8) * 2u;
            ldsm4(kbh, aKh + off);
            ldsm4(kbl, aKl + off);
            mma16816(acc[2 * nb2],     qah[kk], kbh[0], kbh[1]);
            mma16816(acc[2 * nb2],     qah[kk], kbl[0], kbl[1]);
            mma16816(acc[2 * nb2],     qal[kk], kbh[0], kbh[1]);
            mma16816(acc[2 * nb2 + 1], qah[kk], kbh[2], kbh[3]);
            mma16816(acc[2 * nb2 + 1], qah[kk], kbl[2], kbl[3]);
            mma16816(acc[2 * nb2 + 1], qal[kk], kbh[2], kbh[3]);
        }
    }

    const int q4 = lane >> 2, c2 = 2 * (lane & 3);
    float mlo = -1e30f, mhi = -1e30f;
#pragma unroll
    for (int nb = 0; nb < 6; nb++) {
#pragma unroll
        for (int c = 0; c < 4; c++) {
            int rofs = q4 + (c >> 1) * 8;
            int j = 8 * nb + c2 + (c & 1) - rofs;
            int rloc = 16 * w + rofs;
            float sc = ((unsigned)j < 32u)
                           ? acc[nb][c] * 0.125f + sB[rloc * DEG + j]
                           : -1e30f;
            acc[nb][c] = sc;
            if (c < 2) mlo = fmaxf(mlo, sc); else mhi = fmaxf(mhi, sc);
        }
    }
#pragma unroll
    for (int o = 1; o <= 2; o <<= 1) {
        mlo = fmaxf(mlo, __shfl_xor_sync(FULL, mlo, o));
        mhi = fmaxf(mhi, __shfl_xor_sync(FULL, mhi, o));
    }
    float slo = 0.f, shi = 0.f;
#pragma unroll
    for (int nb = 0; nb < 6; nb++) {
#pragma unroll
        for (int c = 0; c < 4; c++) {
            float p = __expf(acc[nb][c] - ((c < 2) ? mlo : mhi));
            acc[nb][c] = p;
            if (c < 2) slo += p; else shi += p;
        }
    }
#pragma unroll
    for (int o = 1; o <= 2; o <<= 1) {
        slo += __shfl_xor_sync(FULL, slo, o);
        shi += __shfl_xor_sync(FULL, shi, o);
    }
    float ilo = 1.f / slo, ihi = 1.f / shi;
#pragma unroll
    for (int nb = 0; nb < 6; nb++) {
        acc[nb][0] *= ilo; acc[nb][1] *= ilo;
        acc[nb][2] *= ihi; acc[nb][3] *= ihi;
    }

    float oacc[8][4];
#pragma unroll
    for (int i = 0; i < 8; i++)
#pragma unroll
        for (int c = 0; c < 4; c++) oacc[i][c] = 0.f;

#pragma unroll
    for (int t3 = 0; t3 < 3; t3++) {
        unsigned pah[4], pal[4];
        split_pack(acc[2 * t3][0],     acc[2 * t3][1],     pah[0], pal[0]);
        split_pack(acc[2 * t3][2],     acc[2 * t3][3],     pah[1], pal[1]);
        split_pack(acc[2 * t3 + 1][0], acc[2 * t3 + 1][1], pah[2], pal[2]);
        split_pack(acc[2 * t3 + 1][2], acc[2 * t3 + 1][3], pah[3], pal[3]);
#pragma unroll
        for (int ng = 0; ng < 4; ng++) {
            unsigned vbh[4], vbl[4];
            unsigned off = (unsigned)((16 * w + 16 * t3 + (lane & 15)) * ATT_LDS
                                      + ng * 16 + (lane >> 4) * 8) * 2u;
            ldsm4t(vbh, aVh + off);
            ldsm4t(vbl, aVl + off);
            mma16816(oacc[2 * ng],     pah, vbh[0], vbh[1]);
            mma16816(oacc[2 * ng],     pah, vbl[0], vbl[1]);
            mma16816(oacc[2 * ng],     pal, vbh[0], vbh[1]);
            mma16816(oacc[2 * ng + 1], pah, vbh[2], vbh[3]);
            mma16816(oacc[2 * ng + 1], pah, vbl[2], vbl[3]);
            mma16816(oacc[2 * ng + 1], pal, vbh[2], vbh[3]);
        }
    }

    int row0 = n0 + 16 * w + q4;
#pragma unroll
    for (int idx = 0; idx < 8; idx++) {
        int col = h * HD + (idx >> 1) * 16 + (idx & 1) * 8 + c2;
        store_split2(oh, ol, (size_t)row0 * HID + col,       oacc[idx][0], oacc[idx][1]);
        store_split2(oh, ol, (size_t)(row0 + 8) * HID + col, oacc[idx][2], oacc[idx][3]);
    }
}

// ---------------- fused residual add + LayerNorm ----------------
__global__ __launch_bounds__(256)
void add_ln_kernel(const float* __restrict__ a, const float* __restrict__ b,
                   const float* __restrict__ g, const float* __restrict__ be,
                   float* __restrict__ out,
                   __nv_bfloat16* __restrict__ ohi, __nv_bfloat16* __restrict__ olo) {
    const unsigned FULL = 0xffffffffu;
    int row  = blockIdx.x * (blockDim.x >> 5) + (threadIdx.x >> 5);
    int lane = threadIdx.x & 31;
    const float* ra = a + (size_t)row * HID;
    const float* rb = b + (size_t)row * HID;

    float vals[8];
    float s = 0.f;
#pragma unroll
    for (int i = 0; i < 8; i++) {
        float v = ra[lane + i * 32] + rb[lane + i * 32];
        vals[i] = v;
        s += v;
    }
#pragma unroll
    for (int o = 16; o > 0; o >>= 1) s += __shfl_xor_sync(FULL, s, o);
    float mean = s * (1.f / HID);

    float var = 0.f;
#pragma unroll
    for (int i = 0; i < 8; i++) {
        float d = vals[i] - mean;
        var += d * d;
    }
#pragma unroll
    for (int o = 16; o > 0; o >>= 1) var += __shfl_xor_sync(FULL, var, o);
    var *= (1.f / HID);
    float inv = rsqrtf(var + 1e-5f);

#pragma unroll
    for (int i = 0; i < 8; i++) {
        int c = lane + i * 32;
        float v = (vals[i] - mean) * inv * g[c] + be[c];
        out[(size_t)row * HID + c] = v;
        if (ohi) {
            __nv_bfloat16 hh = __float2bfloat16_rn(v);
            __nv_bfloat16 ll = __float2bfloat16_rn(v - __bfloat162float(hh));
            ohi[(size_t)row * HID + c] = hh;
            olo[(size_t)row * HID + c] = ll;
        }
    }
}

// ---------------- launch ----------------
extern "C" void kernel_launch(void* const* d_in, const int* in_sizes, int n_in,
                              void* d_out, int out_size) {
    const float* x          = (const float*)d_in[0];
    const int*   edge_index = (const int*)d_in[1];
    const float* edge_attr  = (const float*)d_in[2];
    const float* Wq  = (const float*)d_in[3];
    const float* bq  = (const float*)d_in[4];
    const float* Wk  = (const float*)d_in[5];
    const float* bk  = (const float*)d_in[6];
    const float* Wv  = (const float*)d_in[7];
    const float* bv  = (const float*)d_in[8];
    const float* Wo  = (const float*)d_in[9];
    const float* bo  = (const float*)d_in[10];
    const float* We  = (const float*)d_in[11];
    const float* be  = (const float*)d_in[12];
    const float* g1  = (const float*)d_in[13];
    const float* b1  = (const float*)d_in[14];
    const float* g2  = (const float*)d_in[15];
    const float* b2  = (const float*)d_in[16];
    const float* Wf1 = (const float*)d_in[17];
    const float* bf1 = (const float*)d_in[18];
    const float* Wf2 = (const float*)d_in[19];
    const float* bf2 = (const float*)d_in[20];
    float* out = (float*)d_out;

    float *tmp, *x1, *ebias;
    __nv_bfloat16 *xh, *xl, *wh, *wl, *ah, *al, *x1h, *x1l, *h1h, *h1l;
    __nv_bfloat16 *qh, *ql, *kh, *kl, *vh, *vl;
    cudaGetSymbolAddress((void**)&tmp,   g_tmp);
    cudaGetSymbolAddress((void**)&x1,    g_x1);
    cudaGetSymbolAddress((void**)&ebias, g_ebias);
    cudaGetSymbolAddress((void**)&xh,  g_xh);   cudaGetSymbolAddress((void**)&xl,  g_xl);
    cudaGetSymbolAddress((void**)&wh,  g_wh);   cudaGetSymbolAddress((void**)&wl,  g_wl);
    cudaGetSymbolAddress((void**)&qh,  g_qh);   cudaGetSymbolAddress((void**)&ql,  g_ql);
    cudaGetSymbolAddress((void**)&kh,  g_kh);   cudaGetSymbolAddress((void**)&kl,  g_kl);
    cudaGetSymbolAddress((void**)&vh,  g_vh);   cudaGetSymbolAddress((void**)&vl,  g_vl);
    cudaGetSymbolAddress((void**)&ah,  g_ah);   cudaGetSymbolAddress((void**)&al,  g_al);
    cudaGetSymbolAddress((void**)&x1h, g_x1h);  cudaGetSymbolAddress((void**)&x1l, g_x1l);
    cudaGetSymbolAddress((void**)&h1h, g_h1h);  cudaGetSymbolAddress((void**)&h1l, g_h1l);

    cudaFuncSetAttribute(gemm_tc<32>,  cudaFuncAttributeMaxDynamicSharedMemorySize, SMEM_G32);
    cudaFuncSetAttribute(gemm_tc<64>,  cudaFuncAttributeMaxDynamicSharedMemorySize, SMEM_G64);
    cudaFuncSetAttribute(attn_kernel,  cudaFuncAttributeMaxDynamicSharedMemorySize, SMEM_ATT);

    PrepP pp;
    pp.j[0] = {x,   xh,           xl,           NND * HID / 4};
    pp.j[1] = {Wq,  wh + WOFF_Q,  wl + WOFF_Q,  HID * HID / 4};
    pp.j[2] = {Wk,  wh + WOFF_K,  wl + WOFF_K,  HID * HID / 4};
    pp.j[3] = {Wv,  wh + WOFF_V,  wl + WOFF_V,  HID * HID / 4};
    pp.j[4] = {Wo,  wh + WOFF_O,  wl + WOFF_O,  HID * HID / 4};
    pp.j[5] = {Wf1, wh + WOFF_F1, wl + WOFF_F1, HID * FFN / 4};
    pp.j[6] = {Wf2, wh + WOFF_F2, wl + WOFF_F2, FFN * HID / 4};
    pp.words = edge_index;
    pp.ea = edge_attr; pp.We = We; pp.be = be; pp.ebias = ebias;
    prep_all<<<dim3(192, 9), 256>>>(pp);

    // QKV (z-batched): WN=64, grid 2x32x3 = 192 CTAs
    GemmP pqkv = {};
    pqkv.Ah = xh; pqkv.Al = xl;
    pqkv.Bh[0] = wh + WOFF_Q; pqkv.Bl[0] = wl + WOFF_Q;
    pqkv.Bh[1] = wh + WOFF_K; pqkv.Bl[1] = wl + WOFF_K;
    pqkv.Bh[2] = wh + WOFF_V; pqkv.Bl[2] = wl + WOFF_V;
    pqkv.bias[0] = bq; pqkv.bias[1] = bk; pqkv.bias[2] = bv;
    pqkv.Chi[0] = qh; pqkv.Chi[1] = kh; pqkv.Chi[2] = vh;
    pqkv.Clo[0] = ql; pqkv.Clo[1] = kl; pqkv.Clo[2] = vl;
    gemm_tc<64><<<dim3(HID / 128, NND / 128, 3), 128, SMEM_G64>>>(pqkv, HID, HID, 0);

    attn_kernel<<<dim3(NND / 64, NH), 128, SMEM_ATT>>>(qh, ql, kh, kl, vh, vl, ebias, ah, al);

    // O projection: WN=32, grid 4x32 = 128 CTAs
    GemmP po = {};
    po.Ah = ah; po.Al = al;
    po.Bh[0] = wh + WOFF_O; po.Bl[0] = wl + WOFF_O;
    po.bias[0] = bo;
    po.Cf[0] = tmp;
    gemm_tc<32><<<dim3(HID / 64, NND / 128, 1), 128, SMEM_G32>>>(po, HID, HID, 0);

    add_ln_kernel<<<NND / 8, 256>>>(x, tmp, g1, b1, x1, x1h, x1l);

    // FFN1: WN=64, grid 8x32 = 256 CTAs
    GemmP pf1 = {};
    pf1.Ah = x1h; pf1.Al = x1l;
    pf1.Bh[0] = wh + WOFF_F1; pf1.Bl[0] = wl + WOFF_F1;
    pf1.bias[0] = bf1;
    pf1.Chi[0] = h1h; pf1.Clo[0] = h1l;
    gemm_tc<64><<<dim3(FFN / 128, NND / 128, 1), 128, SMEM_G64>>>(pf1, FFN, HID, 1);

    // FFN2: WN=32, grid 4x32 = 128 CTAs
    GemmP pf2 = {};
    pf2.Ah = h1h; pf2.Al = h1l;
    pf2.Bh[0] = wh + WOFF_F2; pf2.Bl[0] = wl + WOFF_F2;
    pf2.bias[0] = bf2;
    pf2.Cf[0] = tmp;
    gemm_tc<32><<<dim3(HID / 64, NND / 128, 1), 128, SMEM_G32>>>(pf2, HID, FFN, 0);

    add_ln_kernel<<<NND / 8, 256>>>(x1, tmp, g2, b2, out, nullptr, nullptr);
}

// round 12
// speedup vs baseline: 1.0132x; 1.0116x over previous
#include <cuda_runtime.h>
#include <cuda_bf16.h>
#include <cstdint>
#include <math.h>

#define NND   4096
#define HID   256
#define NH    4
#define HD    64
#define DEG   32
#define NE    (NND * DEG)
#define EDIM  16
#define FFN   1024

#define WOFF_Q  0
#define WOFF_K  65536
#define WOFF_V  131072
#define WOFF_O  196608
#define WOFF_F1 262144
#define WOFF_F2 524288

// ---------------- scratch ----------------
__device__ float g_tmp[NND * HID];
__device__ float g_x1[NND * HID];
__device__ int   g_dst[NE];
__device__ int   g_ring = 1;
__device__ float g_ebias[NE * 4];

__device__ __nv_bfloat16 g_xh[NND * HID],  g_xl[NND * HID];
__device__ __nv_bfloat16 g_wh[786432],     g_wl[786432];
__device__ __nv_bfloat16 g_qh[NND * HID],  g_ql[NND * HID];
__device__ __nv_bfloat16 g_kh[NND * HID],  g_kl[NND * HID];
__device__ __nv_bfloat16 g_vh[NND * HID],  g_vl[NND * HID];
__device__ __nv_bfloat16 g_ah[NND * HID],  g_al[NND * HID];
__device__ __nv_bfloat16 g_x1h[NND * HID], g_x1l[NND * HID];
__device__ __nv_bfloat16 g_h1h[NND * FFN], g_h1l[NND * FFN];

// ---------------- merged prep: splits + edge decode + edge bias ----------------
struct SplitJob { const float* src; __nv_bfloat16* hi; __nv_bfloat16* lo; int n4; };
struct PrepP {
    SplitJob j[7];
    const int* words;
    const float *ea, *We, *be;
    float* ebias;
};

__global__ __launch_bounds__(256)
void prep_all(PrepP p) {
    int job = blockIdx.y;
    int stride = gridDim.x * blockDim.x;
    if (job < 7) {
        SplitJob jb = p.j[job];
        for (int i = blockIdx.x * blockDim.x + threadIdx.x; i < jb.n4; i += stride) {
            float4 v = ((const float4*)jb.src)[i];
            float f[4] = {v.x, v.y, v.z, v.w};
            __nv_bfloat16 h[4], l[4];
#pragma unroll
            for (int k = 0; k < 4; k++) {
                h[k] = __float2bfloat16_rn(f[k]);
                l[k] = __float2bfloat16_rn(f[k] - __bfloat162float(h[k]));
            }
            ((ushort4*)jb.hi)[i] = make_ushort4(
                __bfloat16_as_ushort(h[0]), __bfloat16_as_ushort(h[1]),
                __bfloat16_as_ushort(h[2]), __bfloat16_as_ushort(h[3]));
            ((ushort4*)jb.lo)[i] = make_ushort4(
                __bfloat16_as_ushort(l[0]), __bfloat16_as_ushort(l[1]),
                __bfloat16_as_ushort(l[2]), __bfloat16_as_ushort(l[3]));
        }
    } else if (job == 7) {
        for (int e = blockIdx.x * blockDim.x + threadIdx.x; e < NE; e += stride) {
            bool is32 = (p.words[32] == 1);
            int dst = is32 ? p.words[NE + e] : p.words[2 * NE + 2 * e];
            g_dst[e] = dst;
            int expect = ((e / DEG) + 1 + (e % DEG)) & (NND - 1);
            if (dst != expect) g_ring = 0;
        }
    } else {
        for (int e = blockIdx.x * blockDim.x + threadIdx.x; e < NE; e += stride) {
            float a0 = p.be[0], a1 = p.be[1], a2 = p.be[2], a3 = p.be[3];
            const float4* q = (const float4*)(p.ea + (size_t)e * EDIM);
#pragma unroll
            for (int c4 = 0; c4 < 4; c4++) {
                float4 x4 = q[c4];
                float xs[4] = {x4.x, x4.y, x4.z, x4.w};
#pragma unroll
                for (int i = 0; i < 4; i++) {
                    int c = c4 * 4 + i;
                    a0 += xs[i] * p.We[c * NH + 0];
                    a1 += xs[i] * p.We[c * NH + 1];
                    a2 += xs[i] * p.We[c * NH + 2];
                    a3 += xs[i] * p.We[c * NH + 3];
                }
            }
            ((float4*)p.ebias)[e] = make_float4(a0, a1, a2, a3);
        }
    }
}

// ---------------- helpers ----------------
__device__ __forceinline__ void cp16(unsigned dst, const void* src) {
    asm volatile("cp.async.cg.shared.global [%0], [%1], 16;" :: "r"(dst), "l"(src));
}
__device__ __forceinline__ void cpcommit() { asm volatile("cp.async.commit_group;"); }
__device__ __forceinline__ void ldsm4(unsigned r[4], unsigned addr) {
    asm volatile("ldmatrix.sync.aligned.m8n8.x4.shared.b16 {%0,%1,%2,%3}, [%4];"
                 : "=r"(r[0]), "=r"(r[1]), "=r"(r[2]), "=r"(r[3]) : "r"(addr));
}
__device__ __forceinline__ void ldsm4t(unsigned r[4], unsigned addr) {
    asm volatile("ldmatrix.sync.aligned.m8n8.x4.trans.shared.b16 {%0,%1,%2,%3}, [%4];"
                 : "=r"(r[0]), "=r"(r[1]), "=r"(r[2]), "=r"(r[3]) : "r"(addr));
}
__device__ __forceinline__ void mma16816(float c[4], const unsigned a[4],
                                         const unsigned b0, const unsigned b1) {
    asm volatile(
        "mma.sync.aligned.m16n8k16.row.col.f32.bf16.bf16.f32 "
        "{%0,%1,%2,%3}, {%4,%5,%6,%7}, {%8,%9}, {%0,%1,%2,%3};"
        : "+f"(c[0]), "+f"(c[1]), "+f"(c[2]), "+f"(c[3])
        : "r"(a[0]), "r"(a[1]), "r"(a[2]), "r"(a[3]), "r"(b0), "r"(b1));
}
__device__ __forceinline__ void split_pack(float v0, float v1,
                                           unsigned& hi, unsigned& lo) {
    __nv_bfloat16 h0 = __float2bfloat16_rn(v0);
    __nv_bfloat16 h1 = __float2bfloat16_rn(v1);
    __nv_bfloat16 l0 = __float2bfloat16_rn(v0 - __bfloat162float(h0));
    __nv_bfloat16 l1 = __float2bfloat16_rn(v1 - __bfloat162float(h1));
    hi = ((unsigned)__bfloat16_as_ushort(h1) << 16) | __bfloat16_as_ushort(h0);
    lo = ((unsigned)__bfloat16_as_ushort(l1) << 16) | __bfloat16_as_ushort(l0);
}
__device__ __forceinline__ void store_split2(__nv_bfloat16* hi, __nv_bfloat16* lo,
                                             size_t off, float a, float b) {
    __nv_bfloat16 h0 = __float2bfloat16_rn(a), h1 = __float2bfloat16_rn(b);
    __nv_bfloat16 l0 = __float2bfloat16_rn(a - __bfloat162float(h0));
    __nv_bfloat16 l1 = __float2bfloat16_rn(b - __bfloat162float(h1));
    *(ushort2*)(hi + off) = make_ushort2(__bfloat16_as_ushort(h0), __bfloat16_as_ushort(h1));
    *(ushort2*)(lo + off) = make_ushort2(__bfloat16_as_ushort(l0), __bfloat16_as_ushort(l1));
}
__device__ __forceinline__ float2 ld_split2(const __nv_bfloat16* hi, const __nv_bfloat16* lo,
                                            size_t off) {
    ushort2 a = *(const ushort2*)(hi + off);
    ushort2 b = *(const ushort2*)(lo + off);
    return make_float2(
        __bfloat162float(__ushort_as_bfloat16(a.x)) + __bfloat162float(__ushort_as_bfloat16(b.x)),
        __bfloat162float(__ushort_as_bfloat16(a.y)) + __bfloat162float(__ushort_as_bfloat16(b.y)));
}

// =====================================================================
// bf16x3 mma.sync GEMM, templated warp-N.
// WN=32: CTA 128x64, 4 warps @ 64x32, 3 CTAs/SM.
// WN=64: CTA 128x128, 4 warps @ 64x64, 2 CTAs/SM.
// 2-stage cp.async. C ~= Ah*Bh + Ah*Bl + Al*Bh.
// =====================================================================
#define LDA 40
#define A_MATB 10240u             // 128*LDA*2 bytes

struct GemmP {
    const __nv_bfloat16 *Ah, *Al;
    const __nv_bfloat16 *Bh[3], *Bl[3];
    const float* bias[3];
    float* Cf[3];
    __nv_bfloat16* Chi[3];
    __nv_bfloat16* Clo[3];
};

template <int WN>
__global__ __launch_bounds__(128, (WN == 32 ? 3 : 2))
void gemm_tc(GemmP gp, int N, int K, int relu) {
    extern __shared__ __align__(16) __nv_bfloat16 smem[];

    constexpr int BN   = 2 * WN;            // CTA N-tile
    constexpr int LDB  = BN + 8;            // row stride (elems), ≡16B mod 128B
    constexpr unsigned B_MATB = 32u * LDB * 2u;
    constexpr unsigned STGB   = 2u * A_MATB + 2u * B_MATB;
    constexpr int NJ = WN / 8;              // n8 blocks per warp
    constexpr int NG = WN / 16;             // ldsm n16 groups per warp
    constexpr int BCHUNK = BN / 8;          // cp16 per B row
    constexpr int BLOOP  = (32 * BCHUNK) / 128;

    const int z = blockIdx.z;
    const __nv_bfloat16* __restrict__ Ah = gp.Ah;
    const __nv_bfloat16* __restrict__ Al = gp.Al;
    const __nv_bfloat16* __restrict__ Bh = gp.Bh[z];
    const __nv_bfloat16* __restrict__ Bl = gp.Bl[z];

    const int m0 = blockIdx.y * 128;
    const int n0 = blockIdx.x * BN;
    const int t = threadIdx.x, lane = t & 31, w = t >> 5;
    const int wm = (w >> 1) * 64;
    const int wn = (w & 1) * WN;

    const unsigned sb = (unsigned)__cvta_generic_to_shared(smem);

    float acc[4][NJ][4];
#pragma unroll
    for (int i = 0; i < 4; i++)
#pragma unroll
        for (int j = 0; j < NJ; j++)
#pragma unroll
            for (int r = 0; r < 4; r++) acc[i][j][r] = 0.f;

    auto issue = [&](int S) {
        int k0 = S * 32;
        unsigned st = sb + (unsigned)((S & 1) * STGB);
#pragma unroll
        for (int j = 0; j < 4; j++) {
            int id = t + 128 * j;
            int r = id >> 2, c = (id & 3) * 8;
            cp16(st + (r * LDA + c) * 2u,          Ah + (size_t)(m0 + r) * K + k0 + c);
            cp16(st + A_MATB + (r * LDA + c) * 2u, Al + (size_t)(m0 + r) * K + k0 + c);
        }
#pragma unroll
        for (int j = 0; j < BLOOP; j++) {
            int id = t + 128 * j;
            int r = id / BCHUNK, c = (id % BCHUNK) * 8;
            cp16(st + 2 * A_MATB + (r * LDB + c) * 2u,
                 Bh + (size_t)(k0 + r) * N + n0 + c);
            cp16(st + 2 * A_MATB + B_MATB + (r * LDB + c) * 2u,
                 Bl + (size_t)(k0 + r) * N + n0 + c);
        }
        cpcommit();
    };

    const int nst = K >> 5;
    issue(0);

    for (int s = 0; s < nst; s++) {
        if (s + 1 < nst) {
            issue(s + 1);
            asm volatile("cp.async.wait_group 1;" ::: "memory");
        } else {
            asm volatile("cp.async.wait_group 0;" ::: "memory");
        }
        __syncthreads();

        unsigned st = sb + (unsigned)((s & 1) * STGB);
        unsigned a_h = st, a_l = st + A_MATB;
        unsigned b_h = st + 2 * A_MATB, b_l = b_h + B_MATB;

#pragma unroll
        for (int ks = 0; ks < 32; ks += 16) {
            unsigned ah[4][4], al[4][4];
#pragma unroll
            for (int mi = 0; mi < 4; mi++) {
                unsigned off = (unsigned)((wm + mi * 16 + (lane & 15)) * LDA
                                          + ks + (lane >> 4) * 8) * 2u;
                ldsm4(ah[mi], a_h + off);
                ldsm4(al[mi], a_l + off);
            }
            unsigned bh[NG][4], bl[NG][4];
#pragma unroll
            for (int ng = 0; ng < NG; ng++) {
                unsigned off = (unsigned)((ks + (lane & 15)) * LDB
                                          + wn + ng * 16 + (lane >> 4) * 8) * 2u;
                ldsm4t(bh[ng], b_h + off);
                ldsm4t(bl[ng], b_l + off);
            }
#pragma unroll
            for (int mi = 0; mi < 4; mi++)
#pragma unroll
                for (int nj = 0; nj < NJ; nj++) {
                    int ng = nj >> 1, p = (nj & 1) * 2;
                    mma16816(acc[mi][nj], ah[mi], bh[ng][p], bh[ng][p + 1]);
                    mma16816(acc[mi][nj], ah[mi], bl[ng][p], bl[ng][p + 1]);
                    mma16816(acc[mi][nj], al[mi], bh[ng][p], bh[ng][p + 1]);
                }
        }
        __syncthreads();
    }

    const float* __restrict__ bias = gp.bias[z];
    float* __restrict__ Cf  = gp.Cf[z];
    __nv_bfloat16* __restrict__ Chi = gp.Chi[z];
    __nv_bfloat16* __restrict__ Clo = gp.Clo[z];

#pragma unroll
    for (int mi = 0; mi < 4; mi++) {
        int row = m0 + wm + mi * 16 + (lane >> 2);
#pragma unroll
        for (int nj = 0; nj < NJ; nj++) {
            int col = n0 + wn + nj * 8 + (lane & 3) * 2;
            float b0 = bias[col], b1 = bias[col + 1];
            float v0 = acc[mi][nj][0] + b0, v1 = acc[mi][nj][1] + b1;
            float v2 = acc[mi][nj][2] + b0, v3 = acc[mi][nj][3] + b1;
            if (relu) {
                v0 = fmaxf(v0, 0.f); v1 = fmaxf(v1, 0.f);
                v2 = fmaxf(v2, 0.f); v3 = fmaxf(v3, 0.f);
            }
            if (Cf) {
                *(float2*)(Cf + (size_t)row * N + col)       = make_float2(v0, v1);
                *(float2*)(Cf + (size_t)(row + 8) * N + col) = make_float2(v2, v3);
            }
            if (Chi) {
                store_split2(Chi, Clo, (size_t)row * N + col, v0, v1);
                store_split2(Chi, Clo, (size_t)(row + 8) * N + col, v2, v3);
            }
        }
    }
}

#define SMEM_G32 (2 * (2 * 10240 + 2 * (32 * 72 * 2)))
#define SMEM_G64 (2 * (2 * 10240 + 2 * (32 * 136 * 2)))

// =====================================================================
// Attention: fast banded path (ring) + gather fallback, one kernel.
// grid = dim3(NND/64, NH), 128 threads.
// =====================================================================
#define ATT_LDS 72
#define SM_QH 0
#define SM_QL 4608
#define SM_KH 9216
#define SM_KL 16128
#define SM_VH 23040
#define SM_VL 29952
#define SM_BF 36864
#define SMEM_ATT 81920

__global__ __launch_bounds__(128, 2)
void attn_kernel(const __nv_bfloat16* __restrict__ qh, const __nv_bfloat16* __restrict__ ql,
                 const __nv_bfloat16* __restrict__ kh, const __nv_bfloat16* __restrict__ kl,
                 const __nv_bfloat16* __restrict__ vh, const __nv_bfloat16* __restrict__ vl,
                 const float* __restrict__ ebias,
                 __nv_bfloat16* __restrict__ oh, __nv_bfloat16* __restrict__ ol) {
    const unsigned FULL = 0xffffffffu;
    const int t = threadIdx.x, lane = t & 31, w = t >> 5;

    if (!g_ring) {
        // ---- fallback gather path (grid-strided) ----
        int h = w;
        int bid = blockIdx.x + gridDim.x * blockIdx.y;
        int nblocks = gridDim.x * gridDim.y;
        for (int n = bid; n < NND; n += nblocks) {
            int e   = n * DEG + lane;
            int dst = g_dst[e];
            float bias = ebias[(e << 2) + h];
            float2 q2 = ld_split2(qh, ql, (size_t)n * HID + h * HD + lane * 2);
            float myscore = 0.f;
#pragma unroll 4
            for (int j = 0; j < DEG; j++) {
                int dj = __shfl_sync(FULL, dst, j);
                float2 k2 = ld_split2(kh, kl, (size_t)dj * HID + h * HD + lane * 2);
                float p = q2.x * k2.x + q2.y * k2.y;
#pragma unroll
                for (int o = 16; o > 0; o >>= 1) p += __shfl_xor_sync(FULL, p, o);
                if (lane == j) myscore = p;
            }
            myscore = myscore * 0.125f + bias;
            float m = myscore;
#pragma unroll
            for (int o = 16; o > 0; o >>= 1) m = fmaxf(m, __shfl_xor_sync(FULL, m, o));
            float p = __expf(myscore - m);
            float s = p;
#pragma unroll
            for (int o = 16; o > 0; o >>= 1) s += __shfl_xor_sync(FULL, s, o);
            p /= s;
            float2 acc2 = make_float2(0.f, 0.f);
#pragma unroll 4
            for (int j = 0; j < DEG; j++) {
                float pj = __shfl_sync(FULL, p, j);
                int dj   = __shfl_sync(FULL, dst, j);
                float2 v2 = ld_split2(vh, vl, (size_t)dj * HID + h * HD + lane * 2);
                acc2.x += pj * v2.x;
                acc2.y += pj * v2.y;
            }
            store_split2(oh, ol, (size_t)n * HID + h * HD + lane * 2, acc2.x, acc2.y);
        }
        return;
    }

    // ---- fast banded path ----
    extern __shared__ __align__(16) ushort smu[];
    float* sB = (float*)(smu + SM_BF);
    const int h  = blockIdx.y;
    const int n0 = blockIdx.x * 64;

    for (int r = t; r < 256; r += 128) {
        const __nv_bfloat16 *sH = nullptr, *sL = nullptr;
        ushort *dH, *dL;
        if (r < 64) {
            int node = n0 + r;
            sH = qh + (size_t)node * HID + h * HD;
            sL = ql + (size_t)node * HID + h * HD;
            dH = smu + SM_QH + r * ATT_LDS; dL = smu + SM_QL + r * ATT_LDS;
        } else if (r < 160) {
            int i = r - 64;
            dH = smu + SM_KH + i * ATT_LDS; dL = smu + SM_KL + i * ATT_LDS;
            if (i < 95) {
                int node = (n0 + 1 + i) & (NND - 1);
                sH = kh + (size_t)node * HID + h * HD;
                sL = kl + (size_t)node * HID + h * HD;
            }
        } else {
            int i = r - 160;
            dH = smu + SM_VH + i * ATT_LDS; dL = smu + SM_VL + i * ATT_LDS;
            if (i < 95) {
                int node = (n0 + 1 + i) & (NND - 1);
                sH = vh + (size_t)node * HID + h * HD;
                sL = vl + (size_t)node * HID + h * HD;
            }
        }
        if (sH) {
#pragma unroll
            for (int j2 = 0; j2 < 8; j2++) {
                ((uint4*)dH)[j2] = ((const uint4*)sH)[j2];
                ((uint4*)dL)[j2] = ((const uint4*)sL)[j2];
            }
        } else {
            uint4 z4 = make_uint4(0, 0, 0, 0);
#pragma unroll
            for (int j2 = 0; j2 < 8; j2++) { ((uint4*)dH)[j2] = z4; ((uint4*)dL)[j2] = z4; }
        }
    }
    for (int i = t; i < 2048; i += 128)
        sB[i] = ebias[(((size_t)(n0 * DEG + i)) << 2) + h];
    __syncthreads();

    const unsigned base = (unsigned)__cvta_generic_to_shared(smu);
    const unsigned aQh = base + SM_QH * 2u, aQl = base + SM_QL * 2u;
    const unsigned aKh = base + SM_KH * 2u, aKl = base + SM_KL * 2u;
    const unsigned aVh = base + SM_VH * 2u, aVl = base + SM_VL * 2u;

    unsigned qah[4][4], qal[4][4];
#pragma unroll
    for (int kk = 0; kk < 4; kk++) {
        unsigned off = (unsigned)((16 * w + (lane & 15)) * ATT_LDS + kk * 16 + (lane >> 4) * 8) * 2u;
        ldsm4(qah[kk], aQh + off);
        ldsm4(qal[kk], aQl + off);
    }

    float acc[6][4];
#pragma unroll
    for (int i = 0; i < 6; i++)
#pragma unroll
        for (int c = 0; c < 4; c++) acc[i][c] = 0.f;

    const int g2 = lane >> 3, lr = lane & 7;
#pragma unroll
    for (int nb2 = 0; nb2 < 3; nb2++) {
        int n16 = 16 * w + nb2 * 16;
#pragma unroll
        for (int kk = 0; kk < 4; kk++) {
            unsigned kbh[4], kbl[4];
            unsigned off = (unsigned)((n16 + lr + (g2 >> 1) * 8) * ATT_LDS
                                      + kk * 16 + (g2 & 1) * 8) * 2u;
            ldsm4(kbh, aKh + off);
            ldsm4(kbl, aKl + off);
            mma16816(acc[2 * nb2],     qah[kk], kbh[0], kbh[1]);
            mma16816(acc[2 * nb2],     qah[kk], kbl[0], kbl[1]);
            mma16816(acc[2 * nb2],     qal[kk], kbh[0], kbh[1]);
            mma16816(acc[2 * nb2 + 1], qah[kk], kbh[2], kbh[3]);
            mma16816(acc[2 * nb2 + 1], qah[kk], kbl[2], kbl[3]);
            mma16816(acc[2 * nb2 + 1], qal[kk], kbh[2], kbh[3]);
        }
    }

    const int q4 = lane >> 2, c2 = 2 * (lane & 3);
    float mlo = -1e30f, mhi = -1e30f;
#pragma unroll
    for (int nb = 0; nb < 6; nb++) {
#pragma unroll
        for (int c = 0; c < 4; c++) {
            int rofs = q4 + (c >> 1) * 8;
            int j = 8 * nb + c2 + (c & 1) - rofs;
            int rloc = 16 * w + rofs;
            float sc = ((unsigned)j < 32u)
                           ? acc[nb][c] * 0.125f + sB[rloc * DEG + j]
                           : -1e30f;
            acc[nb][c] = sc;
            if (c < 2) mlo = fmaxf(mlo, sc); else mhi = fmaxf(mhi, sc);
        }
    }
#pragma unroll
    for (int o = 1; o <= 2; o <<= 1) {
        mlo = fmaxf(mlo, __shfl_xor_sync(FULL, mlo, o));
        mhi = fmaxf(mhi, __shfl_xor_sync(FULL, mhi, o));
    }
    float slo = 0.f, shi = 0.f;
#pragma unroll
    for (int nb = 0; nb < 6; nb++) {
#pragma unroll
        for (int c = 0; c < 4; c++) {
            float p = __expf(acc[nb][c] - ((c < 2) ? mlo : mhi));
            acc[nb][c] = p;
            if (c < 2) slo += p; else shi += p;
        }
    }
#pragma unroll
    for (int o = 1; o <= 2; o <<= 1) {
        slo += __shfl_xor_sync(FULL, slo, o);
        shi += __shfl_xor_sync(FULL, shi, o);
    }
    float ilo = 1.f / slo, ihi = 1.f / shi;
#pragma unroll
    for (int nb = 0; nb < 6; nb++) {
        acc[nb][0] *= ilo; acc[nb][1] *= ilo;
        acc[nb][2] *= ihi; acc[nb][3] *= ihi;
    }

    float oacc[8][4];
#pragma unroll
    for (int i = 0; i < 8; i++)
#pragma unroll
        for (int c = 0; c < 4; c++) oacc[i][c] = 0.f;

#pragma unroll
    for (int t3 = 0; t3 < 3; t3++) {
        unsigned pah[4], pal[4];
        split_pack(acc[2 * t3][0],     acc[2 * t3][1],     pah[0], pal[0]);
        split_pack(acc[2 * t3][2],     acc[2 * t3][3],     pah[1], pal[1]);
        split_pack(acc[2 * t3 + 1][0], acc[2 * t3 + 1][1], pah[2], pal[2]);
        split_pack(acc[2 * t3 + 1][2], acc[2 * t3 + 1][3], pah[3], pal[3]);
#pragma unroll
        for (int ng = 0; ng < 4; ng++) {
            unsigned vbh[4], vbl[4];
            unsigned off = (unsigned)((16 * w + 16 * t3 + (lane & 15)) * ATT_LDS
                                      + ng * 16 + (lane >> 4) * 8) * 2u;
            ldsm4t(vbh, aVh + off);
            ldsm4t(vbl, aVl + off);
            mma16816(oacc[2 * ng],     pah, vbh[0], vbh[1]);
            mma16816(oacc[2 * ng],     pah, vbl[0], vbl[1]);
            mma16816(oacc[2 * ng],     pal, vbh[0], vbh[1]);
            mma16816(oacc[2 * ng + 1], pah, vbh[2], vbh[3]);
            mma16816(oacc[2 * ng + 1], pah, vbl[2], vbl[3]);
            mma16816(oacc[2 * ng + 1], pal, vbh[2], vbh[3]);
        }
    }

    int row0 = n0 + 16 * w + q4;
#pragma unroll
    for (int idx = 0; idx < 8; idx++) {
        int col = h * HD + (idx >> 1) * 16 + (idx & 1) * 8 + c2;
        store_split2(oh, ol, (size_t)row0 * HID + col,       oacc[idx][0], oacc[idx][1]);
        store_split2(oh, ol, (size_t)(row0 + 8) * HID + col, oacc[idx][2], oacc[idx][3]);
    }
}

// ---------------- fused residual add + LayerNorm ----------------
__global__ __launch_bounds__(256)
void add_ln_kernel(const float* __restrict__ a, const float* __restrict__ b,
                   const float* __restrict__ g, const float* __restrict__ be,
                   float* __restrict__ out,
                   __nv_bfloat16* __restrict__ ohi, __nv_bfloat16* __restrict__ olo) {
    const unsigned FULL = 0xffffffffu;
    int row  = blockIdx.x * (blockDim.x >> 5) + (threadIdx.x >> 5);
    int lane = threadIdx.x & 31;
    const float* ra = a + (size_t)row * HID;
    const float* rb = b + (size_t)row * HID;

    float vals[8];
    float s = 0.f;
#pragma unroll
    for (int i = 0; i < 8; i++) {
        float v = ra[lane + i * 32] + rb[lane + i * 32];
        vals[i] = v;
        s += v;
    }
#pragma unroll
    for (int o = 16; o > 0; o >>= 1) s += __shfl_xor_sync(FULL, s, o);
    float mean = s * (1.f / HID);

    float var = 0.f;
#pragma unroll
    for (int i = 0; i < 8; i++) {
        float d = vals[i] - mean;
        var += d * d;
    }
#pragma unroll
    for (int o = 16; o > 0; o >>= 1) var += __shfl_xor_sync(FULL, var, o);
    var *= (1.f / HID);
    float inv = rsqrtf(var + 1e-5f);

#pragma unroll
    for (int i = 0; i < 8; i++) {
        int c = lane + i * 32;
        float v = (vals[i] - mean) * inv * g[c] + be[c];
        out[(size_t)row * HID + c] = v;
        if (ohi) {
            __nv_bfloat16 hh = __float2bfloat16_rn(v);
            __nv_bfloat16 ll = __float2bfloat16_rn(v - __bfloat162float(hh));
            ohi[(size_t)row * HID + c] = hh;
            olo[(size_t)row * HID + c] = ll;
        }
    }
}

// ---------------- launch ----------------
extern "C" void kernel_launch(void* const* d_in, const int* in_sizes, int n_in,
                              void* d_out, int out_size) {
    const float* x          = (const float*)d_in[0];
    const int*   edge_index = (const int*)d_in[1];
    const float* edge_attr  = (const float*)d_in[2];
    const float* Wq  = (const float*)d_in[3];
    const float* bq  = (const float*)d_in[4];
    const float* Wk  = (const float*)d_in[5];
    const float* bk  = (const float*)d_in[6];
    const float* Wv  = (const float*)d_in[7];
    const float* bv  = (const float*)d_in[8];
    const float* Wo  = (const float*)d_in[9];
    const float* bo  = (const float*)d_in[10];
    const float* We  = (const float*)d_in[11];
    const float* be  = (const float*)d_in[12];
    const float* g1  = (const float*)d_in[13];
    const float* b1  = (const float*)d_in[14];
    const float* g2  = (const float*)d_in[15];
    const float* b2  = (const float*)d_in[16];
    const float* Wf1 = (const float*)d_in[17];
    const float* bf1 = (const float*)d_in[18];
    const float* Wf2 = (const float*)d_in[19];
    const float* bf2 = (const float*)d_in[20];
    float* out = (float*)d_out;

    float *tmp, *x1, *ebias;
    __nv_bfloat16 *xh, *xl, *wh, *wl, *ah, *al, *x1h, *x1l, *h1h, *h1l;
    __nv_bfloat16 *qh, *ql, *kh, *kl, *vh, *vl;
    cudaGetSymbolAddress((void**)&tmp,   g_tmp);
    cudaGetSymbolAddress((void**)&x1,    g_x1);
    cudaGetSymbolAddress((void**)&ebias, g_ebias);
    cudaGetSymbolAddress((void**)&xh,  g_xh);   cudaGetSymbolAddress((void**)&xl,  g_xl);
    cudaGetSymbolAddress((void**)&wh,  g_wh);   cudaGetSymbolAddress((void**)&wl,  g_wl);
    cudaGetSymbolAddress((void**)&qh,  g_qh);   cudaGetSymbolAddress((void**)&ql,  g_ql);
    cudaGetSymbolAddress((void**)&kh,  g_kh);   cudaGetSymbolAddress((void**)&kl,  g_kl);
    cudaGetSymbolAddress((void**)&vh,  g_vh);   cudaGetSymbolAddress((void**)&vl,  g_vl);
    cudaGetSymbolAddress((void**)&ah,  g_ah);   cudaGetSymbolAddress((void**)&al,  g_al);
    cudaGetSymbolAddress((void**)&x1h, g_x1h);  cudaGetSymbolAddress((void**)&x1l, g_x1l);
    cudaGetSymbolAddress((void**)&h1h, g_h1h);  cudaGetSymbolAddress((void**)&h1l, g_h1l);

    cudaFuncSetAttribute(gemm_tc<32>,  cudaFuncAttributeMaxDynamicSharedMemorySize, SMEM_G32);
    cudaFuncSetAttribute(gemm_tc<64>,  cudaFuncAttributeMaxDynamicSharedMemorySize, SMEM_G64);
    cudaFuncSetAttribute(attn_kernel,  cudaFuncAttributeMaxDynamicSharedMemorySize, SMEM_ATT);

    PrepP pp;
    pp.j[0] = {x,   xh,           xl,           NND * HID / 4};
    pp.j[1] = {Wq,  wh + WOFF_Q,  wl + WOFF_Q,  HID * HID / 4};
    pp.j[2] = {Wk,  wh + WOFF_K,  wl + WOFF_K,  HID * HID / 4};
    pp.j[3] = {Wv,  wh + WOFF_V,  wl + WOFF_V,  HID * HID / 4};
    pp.j[4] = {Wo,  wh + WOFF_O,  wl + WOFF_O,  HID * HID / 4};
    pp.j[5] = {Wf1, wh + WOFF_F1, wl + WOFF_F1, HID * FFN / 4};
    pp.j[6] = {Wf2, wh + WOFF_F2, wl + WOFF_F2, FFN * HID / 4};
    pp.words = edge_index;
    pp.ea = edge_attr; pp.We = We; pp.be = be; pp.ebias = ebias;
    prep_all<<<dim3(192, 9), 256>>>(pp);

    // QKV (z-batched): WN=64, grid 2x32x3 = 192 CTAs
    GemmP pqkv = {};
    pqkv.Ah = xh; pqkv.Al = xl;
    pqkv.Bh[0] = wh + WOFF_Q; pqkv.Bl[0] = wl + WOFF_Q;
    pqkv.Bh[1] = wh + WOFF_K; pqkv.Bl[1] = wl + WOFF_K;
    pqkv.Bh[2] = wh + WOFF_V; pqkv.Bl[2] = wl + WOFF_V;
    pqkv.bias[0] = bq; pqkv.bias[1] = bk; pqkv.bias[2] = bv;
    pqkv.Chi[0] = qh; pqkv.Chi[1] = kh; pqkv.Chi[2] = vh;
    pqkv.Clo[0] = ql; pqkv.Clo[1] = kl; pqkv.Clo[2] = vl;
    gemm_tc<64><<<dim3(HID / 128, NND / 128, 3), 128, SMEM_G64>>>(pqkv, HID, HID, 0);

    attn_kernel<<<dim3(NND / 64, NH), 128, SMEM_ATT>>>(qh, ql, kh, kl, vh, vl, ebias, ah, al);

    // O projection: WN=32, grid 4x32 = 128 CTAs
    GemmP po = {};
    po.Ah = ah; po.Al = al;
    po.Bh[0] = wh + WOFF_O; po.Bl[0] = wl + WOFF_O;
    po.bias[0] = bo;
    po.Cf[0] = tmp;
    gemm_tc<32><<<dim3(HID / 64, NND / 128, 1), 128, SMEM_G32>>>(po, HID, HID, 0);

    add_ln_kernel<<<NND / 8, 256>>>(x, tmp, g1, b1, x1, x1h, x1l);

    // FFN1: WN=64, grid 8x32 = 256 CTAs
    GemmP pf1 = {};
    pf1.Ah = x1h; pf1.Al = x1l;
    pf1.Bh[0] = wh + WOFF_F1; pf1.Bl[0] = wl + WOFF_F1;
    pf1.bias[0] = bf1;
    pf1.Chi[0] = h1h; pf1.Clo[0] = h1l;
    gemm_tc<64><<<dim3(FFN / 128, NND / 128, 1), 128, SMEM_G64>>>(pf1, FFN, HID, 1);

    // FFN2: WN=32, grid 4x32 = 128 CTAs
    GemmP pf2 = {};
    pf2.Ah = h1h; pf2.Al = h1l;
    pf2.Bh[0] = wh + WOFF_F2; pf2.Bl[0] = wl + WOFF_F2;
    pf2.bias[0] = bf2;
    pf2.Cf[0] = tmp;
    gemm_tc<32><<<dim3(HID / 64, NND / 128, 1), 128, SMEM_G32>>>(pf2, HID, FFN, 0);

    add_ln_kernel<<<NND / 8, 256>>>(x1, tmp, g2, b2, out, nullptr, nullptr);
}

// round 13
// speedup vs baseline: 1.0159x; 1.0026x over previous
#include <cuda_runtime.h>
#include <cuda_bf16.h>
#include <cstdint>
#include <math.h>

#define NND   4096
#define HID   256
#define NH    4
#define HD    64
#define DEG   32
#define NE    (NND * DEG)
#define EDIM  16
#define FFN   1024

#define WOFF_Q  0
#define WOFF_K  65536
#define WOFF_V  131072
#define WOFF_O  196608
#define WOFF_F1 262144
#define WOFF_F2 524288

// ---------------- scratch ----------------
__device__ float g_tmp[NND * HID];
__device__ float g_x1[NND * HID];
__device__ int   g_dst[NE];
__device__ int   g_ring = 1;
__device__ float g_ebias[NE * 4];

__device__ __nv_bfloat16 g_xh[NND * HID],  g_xl[NND * HID];
__device__ __nv_bfloat16 g_wh[786432],     g_wl[786432];
__device__ __nv_bfloat16 g_qh[NND * HID],  g_ql[NND * HID];
__device__ __nv_bfloat16 g_kh[NND * HID],  g_kl[NND * HID];
__device__ __nv_bfloat16 g_vh[NND * HID],  g_vl[NND * HID];
__device__ __nv_bfloat16 g_ah[NND * HID],  g_al[NND * HID];
__device__ __nv_bfloat16 g_x1h[NND * HID], g_x1l[NND * HID];
__device__ __nv_bfloat16 g_h1h[NND * FFN], g_h1l[NND * FFN];

// ---------------- merged prep: splits + edge decode + edge bias ----------------
struct SplitJob { const float* src; __nv_bfloat16* hi; __nv_bfloat16* lo; int n4; };
struct PrepP {
    SplitJob j[7];
    const int* words;
    const float *ea, *We, *be;
    float* ebias;
};

__global__ __launch_bounds__(256)
void prep_all(PrepP p) {
    int job = blockIdx.y;
    int stride = gridDim.x * blockDim.x;
    if (job < 7) {
        SplitJob jb = p.j[job];
        for (int i = blockIdx.x * blockDim.x + threadIdx.x; i < jb.n4; i += stride) {
            float4 v = ((const float4*)jb.src)[i];
            float f[4] = {v.x, v.y, v.z, v.w};
            __nv_bfloat16 h[4], l[4];
#pragma unroll
            for (int k = 0; k < 4; k++) {
                h[k] = __float2bfloat16_rn(f[k]);
                l[k] = __float2bfloat16_rn(f[k] - __bfloat162float(h[k]));
            }
            ((ushort4*)jb.hi)[i] = make_ushort4(
                __bfloat16_as_ushort(h[0]), __bfloat16_as_ushort(h[1]),
                __bfloat16_as_ushort(h[2]), __bfloat16_as_ushort(h[3]));
            ((ushort4*)jb.lo)[i] = make_ushort4(
                __bfloat16_as_ushort(l[0]), __bfloat16_as_ushort(l[1]),
                __bfloat16_as_ushort(l[2]), __bfloat16_as_ushort(l[3]));
        }
    } else if (job == 7) {
        for (int e = blockIdx.x * blockDim.x + threadIdx.x; e < NE; e += stride) {
            bool is32 = (p.words[32] == 1);
            int dst = is32 ? p.words[NE + e] : p.words[2 * NE + 2 * e];
            g_dst[e] = dst;
            int expect = ((e / DEG) + 1 + (e % DEG)) & (NND - 1);
            if (dst != expect) g_ring = 0;
        }
    } else {
        for (int e = blockIdx.x * blockDim.x + threadIdx.x; e < NE; e += stride) {
            float a0 = p.be[0], a1 = p.be[1], a2 = p.be[2], a3 = p.be[3];
            const float4* q = (const float4*)(p.ea + (size_t)e * EDIM);
#pragma unroll
            for (int c4 = 0; c4 < 4; c4++) {
                float4 x4 = q[c4];
                float xs[4] = {x4.x, x4.y, x4.z, x4.w};
#pragma unroll
                for (int i = 0; i < 4; i++) {
                    int c = c4 * 4 + i;
                    a0 += xs[i] * p.We[c * NH + 0];
                    a1 += xs[i] * p.We[c * NH + 1];
                    a2 += xs[i] * p.We[c * NH + 2];
                    a3 += xs[i] * p.We[c * NH + 3];
                }
            }
            ((float4*)p.ebias)[e] = make_float4(a0, a1, a2, a3);
        }
    }
}

// ---------------- helpers ----------------
__device__ __forceinline__ void cp16(unsigned dst, const void* src) {
    asm volatile("cp.async.cg.shared.global [%0], [%1], 16;" :: "r"(dst), "l"(src));
}
__device__ __forceinline__ void cpcommit() { asm volatile("cp.async.commit_group;"); }
__device__ __forceinline__ void ldsm4(unsigned r[4], unsigned addr) {
    asm volatile("ldmatrix.sync.aligned.m8n8.x4.shared.b16 {%0,%1,%2,%3}, [%4];"
                 : "=r"(r[0]), "=r"(r[1]), "=r"(r[2]), "=r"(r[3]) : "r"(addr));
}
__device__ __forceinline__ void ldsm4t(unsigned r[4], unsigned addr) {
    asm volatile("ldmatrix.sync.aligned.m8n8.x4.trans.shared.b16 {%0,%1,%2,%3}, [%4];"
                 : "=r"(r[0]), "=r"(r[1]), "=r"(r[2]), "=r"(r[3]) : "r"(addr));
}
__device__ __forceinline__ void mma16816(float c[4], const unsigned a[4],
                                         const unsigned b0, const unsigned b1) {
    asm volatile(
        "mma.sync.aligned.m16n8k16.row.col.f32.bf16.bf16.f32 "
        "{%0,%1,%2,%3}, {%4,%5,%6,%7}, {%8,%9}, {%0,%1,%2,%3};"
        : "+f"(c[0]), "+f"(c[1]), "+f"(c[2]), "+f"(c[3])
        : "r"(a[0]), "r"(a[1]), "r"(a[2]), "r"(a[3]), "r"(b0), "r"(b1));
}
__device__ __forceinline__ void split_pack(float v0, float v1,
                                           unsigned& hi, unsigned& lo) {
    __nv_bfloat16 h0 = __float2bfloat16_rn(v0);
    __nv_bfloat16 h1 = __float2bfloat16_rn(v1);
    __nv_bfloat16 l0 = __float2bfloat16_rn(v0 - __bfloat162float(h0));
    __nv_bfloat16 l1 = __float2bfloat16_rn(v1 - __bfloat162float(h1));
    hi = ((unsigned)__bfloat16_as_ushort(h1) << 16) | __bfloat16_as_ushort(h0);
    lo = ((unsigned)__bfloat16_as_ushort(l1) << 16) | __bfloat16_as_ushort(l0);
}
__device__ __forceinline__ void store_split2(__nv_bfloat16* hi, __nv_bfloat16* lo,
                                             size_t off, float a, float b) {
    __nv_bfloat16 h0 = __float2bfloat16_rn(a), h1 = __float2bfloat16_rn(b);
    __nv_bfloat16 l0 = __float2bfloat16_rn(a - __bfloat162float(h0));
    __nv_bfloat16 l1 = __float2bfloat16_rn(b - __bfloat162float(h1));
    *(ushort2*)(hi + off) = make_ushort2(__bfloat16_as_ushort(h0), __bfloat16_as_ushort(h1));
    *(ushort2*)(lo + off) = make_ushort2(__bfloat16_as_ushort(l0), __bfloat16_as_ushort(l1));
}
__device__ __forceinline__ float2 ld_split2(const __nv_bfloat16* hi, const __nv_bfloat16* lo,
                                            size_t off) {
    ushort2 a = *(const ushort2*)(hi + off);
    ushort2 b = *(const ushort2*)(lo + off);
    return make_float2(
        __bfloat162float(__ushort_as_bfloat16(a.x)) + __bfloat162float(__ushort_as_bfloat16(b.x)),
        __bfloat162float(__ushort_as_bfloat16(a.y)) + __bfloat162float(__ushort_as_bfloat16(b.y)));
}

// =====================================================================
// bf16x3 mma.sync GEMM: CTA 128x64, BK=32, 128 thr, 4 warps @ 64x32.
// 2-stage cp.async, 3 CTAs/SM. C ~= Ah*Bh + Ah*Bl + Al*Bh.
// Measured at ~89% of the mma.sync issue ceiling (0.256 GMAC/us).
// =====================================================================
#define LDA 40
#define LDB 72
#define A_MATB 10240u
#define B_MATB 4608u
#define STGB   29696u
#define SMEM_G (2 * 29696)

struct GemmP {
    const __nv_bfloat16 *Ah, *Al;
    const __nv_bfloat16 *Bh[3], *Bl[3];
    const float* bias[3];
    float* Cf[3];
    __nv_bfloat16* Chi[3];
    __nv_bfloat16* Clo[3];
};

__global__ __launch_bounds__(128, 3)
void gemm_tc(GemmP gp, int N, int K, int relu) {
    extern __shared__ __align__(16) __nv_bfloat16 smem[];

    const int z = blockIdx.z;
    const __nv_bfloat16* __restrict__ Ah = gp.Ah;
    const __nv_bfloat16* __restrict__ Al = gp.Al;
    const __nv_bfloat16* __restrict__ Bh = gp.Bh[z];
    const __nv_bfloat16* __restrict__ Bl = gp.Bl[z];

    const int m0 = blockIdx.y * 128;
    const int n0 = blockIdx.x * 64;
    const int t = threadIdx.x, lane = t & 31, w = t >> 5;
    const int wm = (w >> 1) * 64;
    const int wn = (w & 1) * 32;

    const unsigned sb = (unsigned)__cvta_generic_to_shared(smem);

    float acc[4][4][4];
#pragma unroll
    for (int i = 0; i < 4; i++)
#pragma unroll
        for (int j = 0; j < 4; j++)
#pragma unroll
            for (int r = 0; r < 4; r++) acc[i][j][r] = 0.f;

    auto issue = [&](int S) {
        int k0 = S * 32;
        unsigned st = sb + (unsigned)((S & 1) * STGB);
#pragma unroll
        for (int j = 0; j < 4; j++) {
            int id = t + 128 * j;
            int r = id >> 2, c = (id & 3) * 8;
            cp16(st + (r * LDA + c) * 2u,          Ah + (size_t)(m0 + r) * K + k0 + c);
            cp16(st + A_MATB + (r * LDA + c) * 2u, Al + (size_t)(m0 + r) * K + k0 + c);
        }
#pragma unroll
        for (int j = 0; j < 2; j++) {
            int id = t + 128 * j;
            int r = id >> 3, c = (id & 7) * 8;
            cp16(st + 2 * A_MATB + (r * LDB + c) * 2u,
                 Bh + (size_t)(k0 + r) * N + n0 + c);
            cp16(st + 2 * A_MATB + B_MATB + (r * LDB + c) * 2u,
                 Bl + (size_t)(k0 + r) * N + n0 + c);
        }
        cpcommit();
    };

    const int nst = K >> 5;
    issue(0);

    for (int s = 0; s < nst; s++) {
        if (s + 1 < nst) {
            issue(s + 1);
            asm volatile("cp.async.wait_group 1;" ::: "memory");
        } else {
            asm volatile("cp.async.wait_group 0;" ::: "memory");
        }
        __syncthreads();

        unsigned st = sb + (unsigned)((s & 1) * STGB);
        unsigned a_h = st, a_l = st + A_MATB;
        unsigned b_h = st + 2 * A_MATB, b_l = b_h + B_MATB;

#pragma unroll
        for (int ks = 0; ks < 32; ks += 16) {
            unsigned ah[4][4], al[4][4];
#pragma unroll
            for (int mi = 0; mi < 4; mi++) {
                unsigned off = (unsigned)((wm + mi * 16 + (lane & 15)) * LDA
                                          + ks + (lane >> 4) * 8) * 2u;
                ldsm4(ah[mi], a_h + off);
                ldsm4(al[mi], a_l + off);
            }
            unsigned bh[2][4], bl[2][4];
#pragma unroll
            for (int ng = 0; ng < 2; ng++) {
                unsigned off = (unsigned)((ks + (lane & 15)) * LDB
                                          + wn + ng * 16 + (lane >> 4) * 8) * 2u;
                ldsm4t(bh[ng], b_h + off);
                ldsm4t(bl[ng], b_l + off);
            }
#pragma unroll
            for (int mi = 0; mi < 4; mi++)
#pragma unroll
                for (int nj = 0; nj < 4; nj++) {
                    int ng = nj >> 1, p = (nj & 1) * 2;
                    mma16816(acc[mi][nj], ah[mi], bh[ng][p], bh[ng][p + 1]);
                    mma16816(acc[mi][nj], ah[mi], bl[ng][p], bl[ng][p + 1]);
                    mma16816(acc[mi][nj], al[mi], bh[ng][p], bh[ng][p + 1]);
                }
        }
        __syncthreads();
    }

    const float* __restrict__ bias = gp.bias[z];
    float* __restrict__ Cf  = gp.Cf[z];
    __nv_bfloat16* __restrict__ Chi = gp.Chi[z];
    __nv_bfloat16* __restrict__ Clo = gp.Clo[z];

#pragma unroll
    for (int mi = 0; mi < 4; mi++) {
        int row = m0 + wm + mi * 16 + (lane >> 2);
#pragma unroll
        for (int nj = 0; nj < 4; nj++) {
            int col = n0 + wn + nj * 8 + (lane & 3) * 2;
            float b0 = bias[col], b1 = bias[col + 1];
            float v0 = acc[mi][nj][0] + b0, v1 = acc[mi][nj][1] + b1;
            float v2 = acc[mi][nj][2] + b0, v3 = acc[mi][nj][3] + b1;
            if (relu) {
                v0 = fmaxf(v0, 0.f); v1 = fmaxf(v1, 0.f);
                v2 = fmaxf(v2, 0.f); v3 = fmaxf(v3, 0.f);
            }
            if (Cf) {
                *(float2*)(Cf + (size_t)row * N + col)       = make_float2(v0, v1);
                *(float2*)(Cf + (size_t)(row + 8) * N + col) = make_float2(v2, v3);
            }
            if (Chi) {
                store_split2(Chi, Clo, (size_t)row * N + col, v0, v1);
                store_split2(Chi, Clo, (size_t)(row + 8) * N + col, v2, v3);
            }
        }
    }
}

// =====================================================================
// Attention: fast banded path (ring) + gather fallback, one kernel.
// =====================================================================
#define ATT_LDS 72
#define SM_QH 0
#define SM_QL 4608
#define SM_KH 9216
#define SM_KL 16128
#define SM_VH 23040
#define SM_VL 29952
#define SM_BF 36864
#define SMEM_ATT 81920

__global__ __launch_bounds__(128, 2)
void attn_kernel(const __nv_bfloat16* __restrict__ qh, const __nv_bfloat16* __restrict__ ql,
                 const __nv_bfloat16* __restrict__ kh, const __nv_bfloat16* __restrict__ kl,
                 const __nv_bfloat16* __restrict__ vh, const __nv_bfloat16* __restrict__ vl,
                 const float* __restrict__ ebias,
                 __nv_bfloat16* __restrict__ oh, __nv_bfloat16* __restrict__ ol) {
    const unsigned FULL = 0xffffffffu;
    const int t = threadIdx.x, lane = t & 31, w = t >> 5;

    if (!g_ring) {
        int h = w;
        int bid = blockIdx.x + gridDim.x * blockIdx.y;
        int nblocks = gridDim.x * gridDim.y;
        for (int n = bid; n < NND; n += nblocks) {
            int e   = n * DEG + lane;
            int dst = g_dst[e];
            float bias = ebias[(e << 2) + h];
            float2 q2 = ld_split2(qh, ql, (size_t)n * HID + h * HD + lane * 2);
            float myscore = 0.f;
#pragma unroll 4
            for (int j = 0; j < DEG; j++) {
                int dj = __shfl_sync(FULL, dst, j);
                float2 k2 = ld_split2(kh, kl, (size_t)dj * HID + h * HD + lane * 2);
                float p = q2.x * k2.x + q2.y * k2.y;
#pragma unroll
                for (int o = 16; o > 0; o >>= 1) p += __shfl_xor_sync(FULL, p, o);
                if (lane == j) myscore = p;
            }
            myscore = myscore * 0.125f + bias;
            float m = myscore;
#pragma unroll
            for (int o = 16; o > 0; o >>= 1) m = fmaxf(m, __shfl_xor_sync(FULL, m, o));
            float p = __expf(myscore - m);
            float s = p;
#pragma unroll
            for (int o = 16; o > 0; o >>= 1) s += __shfl_xor_sync(FULL, s, o);
            p /= s;
            float2 acc2 = make_float2(0.f, 0.f);
#pragma unroll 4
            for (int j = 0; j < DEG; j++) {
                float pj = __shfl_sync(FULL, p, j);
                int dj   = __shfl_sync(FULL, dst, j);
                float2 v2 = ld_split2(vh, vl, (size_t)dj * HID + h * HD + lane * 2);
                acc2.x += pj * v2.x;
                acc2.y += pj * v2.y;
            }
            store_split2(oh, ol, (size_t)n * HID + h * HD + lane * 2, acc2.x, acc2.y);
        }
        return;
    }

    extern __shared__ __align__(16) ushort smu[];
    float* sB = (float*)(smu + SM_BF);
    const int h  = blockIdx.y;
    const int n0 = blockIdx.x * 64;

    for (int r = t; r < 256; r += 128) {
        const __nv_bfloat16 *sH = nullptr, *sL = nullptr;
        ushort *dH, *dL;
        if (r < 64) {
            int node = n0 + r;
            sH = qh + (size_t)node * HID + h * HD;
            sL = ql + (size_t)node * HID + h * HD;
            dH = smu + SM_QH + r * ATT_LDS; dL = smu + SM_QL + r * ATT_LDS;
        } else if (r < 160) {
            int i = r - 64;
            dH = smu + SM_KH + i * ATT_LDS; dL = smu + SM_KL + i * ATT_LDS;
            if (i < 95) {
                int node = (n0 + 1 + i) & (NND - 1);
                sH = kh + (size_t)node * HID + h * HD;
                sL = kl + (size_t)node * HID + h * HD;
            }
        } else {
            int i = r - 160;
            dH = smu + SM_VH + i * ATT_LDS; dL = smu + SM_VL + i * ATT_LDS;
            if (i < 95) {
                int node = (n0 + 1 + i) & (NND - 1);
                sH = vh + (size_t)node * HID + h * HD;
                sL = vl + (size_t)node * HID + h * HD;
            }
        }
        if (sH) {
#pragma unroll
            for (int j2 = 0; j2 < 8; j2++) {
                ((uint4*)dH)[j2] = ((const uint4*)sH)[j2];
                ((uint4*)dL)[j2] = ((const uint4*)sL)[j2];
            }
        } else {
            uint4 z4 = make_uint4(0, 0, 0, 0);
#pragma unroll
            for (int j2 = 0; j2 < 8; j2++) { ((uint4*)dH)[j2] = z4; ((uint4*)dL)[j2] = z4; }
        }
    }
    for (int i = t; i < 2048; i += 128)
        sB[i] = ebias[(((size_t)(n0 * DEG + i)) << 2) + h];
    __syncthreads();

    const unsigned base = (unsigned)__cvta_generic_to_shared(smu);
    const unsigned aQh = base + SM_QH * 2u, aQl = base + SM_QL * 2u;
    const unsigned aKh = base + SM_KH * 2u, aKl = base + SM_KL * 2u;
    const unsigned aVh = base + SM_VH * 2u, aVl = base + SM_VL * 2u;

    unsigned qah[4][4], qal[4][4];
#pragma unroll
    for (int kk = 0; kk < 4; kk++) {
        unsigned off = (unsigned)((16 * w + (lane & 15)) * ATT_LDS + kk * 16 + (lane >> 4) * 8) * 2u;
        ldsm4(qah[kk], aQh + off);
        ldsm4(qal[kk], aQl + off);
    }

    float acc[6][4];
#pragma unroll
    for (int i = 0; i < 6; i++)
#pragma unroll
        for (int c = 0; c < 4; c++) acc[i][c] = 0.f;

    const int g2 = lane >> 3, lr = lane & 7;
#pragma unroll
    for (int nb2 = 0; nb2 < 3; nb2++) {
        int n16 = 16 * w + nb2 * 16;
#pragma unroll
        for (int kk = 0; kk < 4; kk++) {
            unsigned kbh[4], kbl[4];
            unsigned off = (unsigned)((n16 + lr + (g2 >> 1) * 8) * ATT_LDS
                                      + kk * 16 + (g2 & 1) * 8) * 2u;
            ldsm4(kbh, aKh + off);
            ldsm4(kbl, aKl + off);
            mma16816(acc[2 * nb2],     qah[kk], kbh[0], kbh[1]);
            mma16816(acc[2 * nb2],     qah[kk], kbl[0], kbl[1]);
            mma16816(acc[2 * nb2],     qal[kk], kbh[0], kbh[1]);
            mma16816(acc[2 * nb2 + 1], qah[kk], kbh[2], kbh[3]);
            mma16816(acc[2 * nb2 + 1], qah[kk], kbl[2], kbl[3]);
            mma16816(acc[2 * nb2 + 1], qal[kk], kbh[2], kbh[3]);
        }
    }

    const int q4 = lane >> 2, c2 = 2 * (lane & 3);
    float mlo = -1e30f, mhi = -1e30f;
#pragma unroll
    for (int nb = 0; nb < 6; nb++) {
#pragma unroll
        for (int c = 0; c < 4; c++) {
            int rofs = q4 + (c >> 1) * 8;
            int j = 8 * nb + c2 + (c & 1) - rofs;
            int rloc = 16 * w + rofs;
            float sc = ((unsigned)j < 32u)
                           ? acc[nb][c] * 0.125f + sB[rloc * DEG + j]
                           : -1e30f;
            acc[nb][c] = sc;
            if (c < 2) mlo = fmaxf(mlo, sc); else mhi = fmaxf(mhi, sc);
        }
    }
#pragma unroll
    for (int o = 1; o <= 2; o <<= 1) {
        mlo = fmaxf(mlo, __shfl_xor_sync(FULL, mlo, o));
        mhi = fmaxf(mhi, __shfl_xor_sync(FULL, mhi, o));
    }
    float slo = 0.f, shi = 0.f;
#pragma unroll
    for (int nb = 0; nb < 6; nb++) {
#pragma unroll
        for (int c = 0; c < 4; c++) {
            float p = __expf(acc[nb][c] - ((c < 2) ? mlo : mhi));
            acc[nb][c] = p;
            if (c < 2) slo += p; else shi += p;
        }
    }
#pragma unroll
    for (int o = 1; o <= 2; o <<= 1) {
        slo += __shfl_xor_sync(FULL, slo, o);
        shi += __shfl_xor_sync(FULL, shi, o);
    }
    float ilo = 1.f / slo, ihi = 1.f / shi;
#pragma unroll
    for (int nb = 0; nb < 6; nb++) {
        acc[nb][0] *= ilo; acc[nb][1] *= ilo;
        acc[nb][2] *= ihi; acc[nb][3] *= ihi;
    }

    float oacc[8][4];
#pragma unroll
    for (int i = 0; i < 8; i++)
#pragma unroll
        for (int c = 0; c < 4; c++) oacc[i][c] = 0.f;

#pragma unroll
    for (int t3 = 0; t3 < 3; t3++) {
        unsigned pah[4], pal[4];
        split_pack(acc[2 * t3][0],     acc[2 * t3][1],     pah[0], pal[0]);
        split_pack(acc[2 * t3][2],     acc[2 * t3][3],     pah[1], pal[1]);
        split_pack(acc[2 * t3 + 1][0], acc[2 * t3 + 1][1], pah[2], pal[2]);
        split_pack(acc[2 * t3 + 1][2], acc[2 * t3 + 1][3], pah[3], pal[3]);
#pragma unroll
        for (int ng = 0; ng < 4; ng++) {
            unsigned vbh[4], vbl[4];
            unsigned off = (unsigned)((16 * w + 16 * t3 + (lane & 15)) * ATT_LDS
                                      + ng * 16 + (lane >> 4) * 8) * 2u;
            ldsm4t(vbh, aVh + off);
            ldsm4t(vbl, aVl + off);
            mma16816(oacc[2 * ng],     pah, vbh[0], vbh[1]);
            mma16816(oacc[2 * ng],     pah, vbl[0], vbl[1]);
            mma16816(oacc[2 * ng],     pal, vbh[0], vbh[1]);
            mma16816(oacc[2 * ng + 1], pah, vbh[2], vbh[3]);
            mma16816(oacc[2 * ng + 1], pah, vbl[2], vbl[3]);
            mma16816(oacc[2 * ng + 1], pal, vbh[2], vbh[3]);
        }
    }

    int row0 = n0 + 16 * w + q4;
#pragma unroll
    for (int idx = 0; idx < 8; idx++) {
        int col = h * HD + (idx >> 1) * 16 + (idx & 1) * 8 + c2;
        store_split2(oh, ol, (size_t)row0 * HID + col,       oacc[idx][0], oacc[idx][1]);
        store_split2(oh, ol, (size_t)(row0 + 8) * HID + col, oacc[idx][2], oacc[idx][3]);
    }
}

// ---------------- fused residual add + LayerNorm ----------------
__global__ __launch_bounds__(256)
void add_ln_kernel(const float* __restrict__ a, const float* __restrict__ b,
                   const float* __restrict__ g, const float* __restrict__ be,
                   float* __restrict__ out,
                   __nv_bfloat16* __restrict__ ohi, __nv_bfloat16* __restrict__ olo) {
    const unsigned FULL = 0xffffffffu;
    int row  = blockIdx.x * (blockDim.x >> 5) + (threadIdx.x >> 5);
    int lane = threadIdx.x & 31;
    const float* ra = a + (size_t)row * HID;
    const float* rb = b + (size_t)row * HID;

    float vals[8];
    float s = 0.f;
#pragma unroll
    for (int i = 0; i < 8; i++) {
        float v = ra[lane + i * 32] + rb[lane + i * 32];
        vals[i] = v;
        s += v;
    }
#pragma unroll
    for (int o = 16; o > 0; o >>= 1) s += __shfl_xor_sync(FULL, s, o);
    float mean = s * (1.f / HID);

    float var = 0.f;
#pragma unroll
    for (int i = 0; i < 8; i++) {
        float d = vals[i] - mean;
        var += d * d;
    }
#pragma unroll
    for (int o = 16; o > 0; o >>= 1) var += __shfl_xor_sync(FULL, var, o);
    var *= (1.f / HID);
    float inv = rsqrtf(var + 1e-5f);

#pragma unroll
    for (int i = 0; i < 8; i++) {
        int c = lane + i * 32;
        float v = (vals[i] - mean) * inv * g[c] + be[c];
        out[(size_t)row * HID + c] = v;
        if (ohi) {
            __nv_bfloat16 hh = __float2bfloat16_rn(v);
            __nv_bfloat16 ll = __float2bfloat16_rn(v - __bfloat162float(hh));
            ohi[(size_t)row * HID + c] = hh;
            olo[(size_t)row * HID + c] = ll;
        }
    }
}

// ---------------- launch ----------------
extern "C" void kernel_launch(void* const* d_in, const int* in_sizes, int n_in,
                              void* d_out, int out_size) {
    const float* x          = (const float*)d_in[0];
    const int*   edge_index = (const int*)d_in[1];
    const float* edge_attr  = (const float*)d_in[2];
    const float* Wq  = (const float*)d_in[3];
    const float* bq  = (const float*)d_in[4];
    const float* Wk  = (const float*)d_in[5];
    const float* bk  = (const float*)d_in[6];
    const float* Wv  = (const float*)d_in[7];
    const float* bv  = (const float*)d_in[8];
    const float* Wo  = (const float*)d_in[9];
    const float* bo  = (const float*)d_in[10];
    const float* We  = (const float*)d_in[11];
    const float* be  = (const float*)d_in[12];
    const float* g1  = (const float*)d_in[13];
    const float* b1  = (const float*)d_in[14];
    const float* g2  = (const float*)d_in[15];
    const float* b2  = (const float*)d_in[16];
    const float* Wf1 = (const float*)d_in[17];
    const float* bf1 = (const float*)d_in[18];
    const float* Wf2 = (const float*)d_in[19];
    const float* bf2 = (const float*)d_in[20];
    float* out = (float*)d_out;

    float *tmp, *x1, *ebias;
    __nv_bfloat16 *xh, *xl, *wh, *wl, *ah, *al, *x1h, *x1l, *h1h, *h1l;
    __nv_bfloat16 *qh, *ql, *kh, *kl, *vh, *vl;
    cudaGetSymbolAddress((void**)&tmp,   g_tmp);
    cudaGetSymbolAddress((void**)&x1,    g_x1);
    cudaGetSymbolAddress((void**)&ebias, g_ebias);
    cudaGetSymbolAddress((void**)&xh,  g_xh);   cudaGetSymbolAddress((void**)&xl,  g_xl);
    cudaGetSymbolAddress((void**)&wh,  g_wh);   cudaGetSymbolAddress((void**)&wl,  g_wl);
    cudaGetSymbolAddress((void**)&qh,  g_qh);   cudaGetSymbolAddress((void**)&ql,  g_ql);
    cudaGetSymbolAddress((void**)&kh,  g_kh);   cudaGetSymbolAddress((void**)&kl,  g_kl);
    cudaGetSymbolAddress((void**)&vh,  g_vh);   cudaGetSymbolAddress((void**)&vl,  g_vl);
    cudaGetSymbolAddress((void**)&ah,  g_ah);   cudaGetSymbolAddress((void**)&al,  g_al);
    cudaGetSymbolAddress((void**)&x1h, g_x1h);  cudaGetSymbolAddress((void**)&x1l, g_x1l);
    cudaGetSymbolAddress((void**)&h1h, g_h1h);  cudaGetSymbolAddress((void**)&h1l, g_h1l);

    cudaFuncSetAttribute(gemm_tc,     cudaFuncAttributeMaxDynamicSharedMemorySize, SMEM_G);
    cudaFuncSetAttribute(attn_kernel, cudaFuncAttributeMaxDynamicSharedMemorySize, SMEM_ATT);

    PrepP pp;
    pp.j[0] = {x,   xh,           xl,           NND * HID / 4};
    pp.j[1] = {Wq,  wh + WOFF_Q,  wl + WOFF_Q,  HID * HID / 4};
    pp.j[2] = {Wk,  wh + WOFF_K,  wl + WOFF_K,  HID * HID / 4};
    pp.j[3] = {Wv,  wh + WOFF_V,  wl + WOFF_V,  HID * HID / 4};
    pp.j[4] = {Wo,  wh + WOFF_O,  wl + WOFF_O,  HID * HID / 4};
    pp.j[5] = {Wf1, wh + WOFF_F1, wl + WOFF_F1, HID * FFN / 4};
    pp.j[6] = {Wf2, wh + WOFF_F2, wl + WOFF_F2, FFN * HID / 4};
    pp.words = edge_index;
    pp.ea = edge_attr; pp.We = We; pp.be = be; pp.ebias = ebias;
    prep_all<<<dim3(192, 9), 256>>>(pp);

    // QKV (z-batched): grid 4x32x3 = 384 CTAs, 3/SM
    GemmP pqkv = {};
    pqkv.Ah = xh; pqkv.Al = xl;
    pqkv.Bh[0] = wh + WOFF_Q; pqkv.Bl[0] = wl + WOFF_Q;
    pqkv.Bh[1] = wh + WOFF_K; pqkv.Bl[1] = wl + WOFF_K;
    pqkv.Bh[2] = wh + WOFF_V; pqkv.Bl[2] = wl + WOFF_V;
    pqkv.bias[0] = bq; pqkv.bias[1] = bk; pqkv.bias[2] = bv;
    pqkv.Chi[0] = qh; pqkv.Chi[1] = kh; pqkv.Chi[2] = vh;
    pqkv.Clo[0] = ql; pqkv.Clo[1] = kl; pqkv.Clo[2] = vl;
    gemm_tc<<<dim3(HID / 64, NND / 128, 3), 128, SMEM_G>>>(pqkv, HID, HID, 0);

    attn_kernel<<<dim3(NND / 64, NH), 128, SMEM_ATT>>>(qh, ql, kh, kl, vh, vl, ebias, ah, al);

    // O projection: grid 128
    GemmP po = {};
    po.Ah = ah; po.Al = al;
    po.Bh[0] = wh + WOFF_O; po.Bl[0] = wl + WOFF_O;
    po.bias[0] = bo;
    po.Cf[0] = tmp;
    gemm_tc<<<dim3(HID / 64, NND / 128, 1), 128, SMEM_G>>>(po, HID, HID, 0);

    add_ln_kernel<<<NND / 8, 256>>>(x, tmp, g1, b1, x1, x1h, x1l);

    // FFN1: grid 512
    GemmP pf1 = {};
    pf1.Ah = x1h; pf1.Al = x1l;
    pf1.Bh[0] = wh + WOFF_F1; pf1.Bl[0] = wl + WOFF_F1;
    pf1.bias[0] = bf1;
    pf1.Chi[0] = h1h; pf1.Clo[0] = h1l;
    gemm_tc<<<dim3(FFN / 64, NND / 128, 1), 128, SMEM_G>>>(pf1, FFN, HID, 1);

    // FFN2: grid 128
    GemmP pf2 = {};
    pf2.Ah = h1h; pf2.Al = h1l;
    pf2.Bh[0] = wh + WOFF_F2; pf2.Bl[0] = wl + WOFF_F2;
    pf2.bias[0] = bf2;
    pf2.Cf[0] = tmp;
    gemm_tc<<<dim3(HID / 64, NND / 128, 1), 128, SMEM_G>>>(pf2, HID, FFN, 0);

    add_ln_kernel<<<NND / 8, 256>>>(x1, tmp, g2, b2, out, nullptr, nullptr);
}